// round 12
// baseline (speedup 1.0000x reference)
#include <cuda_runtime.h>
#include <cuda_bf16.h>
#include <cstdint>

// Shapes (fixed per reference)
#define B_SZ     8192
#define K_SZ     50
#define KG_DIM   64
#define IN_SZ    512
#define CC       64
#define OUT_SZ   1024

// ---------------------------------------------------------------------------
// Scratch (static device globals -- no runtime allocation allowed)
// ---------------------------------------------------------------------------
__device__ __align__(16) float g_h1[B_SZ * 128];
__device__ __align__(16) float g_h2[B_SZ * 512];
__device__ __align__(16) float g_h3[B_SZ * 128];
__device__ __align__(16) float g_h4[B_SZ * CC];
__device__ __align__(16) float g_know[B_SZ * CC];
__device__ __align__(16) float g_xt[B_SZ * IN_SZ];   // tf32-rounded x
__device__ __align__(16) float g_wt[270336];         // tf32-rounded weights (packed)
__device__ int   g_cnt[B_SZ];
__device__ int   g_cidx[B_SZ * K_SZ];

// packed weight offsets (floats)
#define W1A_OFF 0
#define W1B_OFF 65536
#define W1C_OFF 131072
#define W1D_OFF 196608
#define W2_OFF  204800

// ---------------------------------------------------------------------------
// tf32 / mma / cp.async helpers
// ---------------------------------------------------------------------------
__device__ __forceinline__ float to_tf32(float x) {
    uint32_t u;
    asm("cvt.rna.tf32.f32 %0, %1;" : "=r"(u) : "f"(x));
    return __uint_as_float(u);
}
__device__ __forceinline__ float4 cvt4(float4 v) {
    return make_float4(to_tf32(v.x), to_tf32(v.y), to_tf32(v.z), to_tf32(v.w));
}
__device__ __forceinline__ void mma_tf32(float* d, const uint32_t* a, const uint32_t* b) {
    asm volatile(
        "mma.sync.aligned.m16n8k8.row.col.f32.tf32.tf32.f32 "
        "{%0,%1,%2,%3}, {%4,%5,%6,%7}, {%8,%9}, {%0,%1,%2,%3};"
        : "+f"(d[0]), "+f"(d[1]), "+f"(d[2]), "+f"(d[3])
        : "r"(a[0]), "r"(a[1]), "r"(a[2]), "r"(a[3]), "r"(b[0]), "r"(b[1]));
}
__device__ __forceinline__ void cp16(void* smem_dst, const void* gsrc) {
    unsigned s = (unsigned)__cvta_generic_to_shared(smem_dst);
    asm volatile("cp.async.ca.shared.global [%0], [%1], 16;" :: "r"(s), "l"(gsrc));
}
__device__ __forceinline__ void cp_commit() { asm volatile("cp.async.commit_group;"); }
__device__ __forceinline__ void cp_wait0()  { asm volatile("cp.async.wait_group 0;"); }

// ---------------------------------------------------------------------------
// Kernel 0: preconvert x and all weights to tf32 (rna) once.
// x: 1048576 float4s -> g_xt.  Weights: 67584 float4s -> g_wt (packed).
// ---------------------------------------------------------------------------
__global__ void __launch_bounds__(256) preconvert_kernel(
    const float* __restrict__ x,
    const float* __restrict__ W1a, const float* __restrict__ W1b,
    const float* __restrict__ W1c, const float* __restrict__ W1d,
    const float* __restrict__ W2)
{
    const int XT_F4 = (B_SZ * IN_SZ) / 4;   // 1048576
    int i4 = blockIdx.x * 256 + threadIdx.x;
    if (i4 < XT_F4) {
        ((float4*)g_xt)[i4] = cvt4(((const float4*)x)[i4]);
        return;
    }
    int j = i4 - XT_F4;
    const float* src; int dst;
    if      (j < 16384) { src = W1a; dst = W1A_OFF / 4; }
    else if (j < 32768) { src = W1b; dst = W1B_OFF / 4; j -= 16384; }
    else if (j < 49152) { src = W1c; dst = W1C_OFF / 4; j -= 32768; }
    else if (j < 51200) { src = W1d; dst = W1D_OFF / 4; j -= 49152; }
    else                { src = W2;  dst = W2_OFF  / 4; j -= 51200; }
    ((float4*)g_wt)[dst + j] = cvt4(((const float4*)src)[j]);
}

// ---------------------------------------------------------------------------
// Kernel 1: warp-per-row compaction of masked gather indices.
// ---------------------------------------------------------------------------
__global__ void __launch_bounds__(256) compact_kernel(
    const int* __restrict__ idx, const int* __restrict__ mask,
    int* __restrict__ cidx, int* __restrict__ cnt)
{
    int b = blockIdx.x * (blockDim.x >> 5) + (threadIdx.x >> 5);
    if (b >= B_SZ) return;
    int l = threadIdx.x & 31;
    int base = b * K_SZ;
    int c = 0;
    #pragma unroll
    for (int k0 = 0; k0 < K_SZ; k0 += 32) {
        int k = k0 + l;
        bool m = (k < K_SZ) && (mask[base + k] != 0);
        unsigned bal = __ballot_sync(0xffffffffu, m);
        int pos = c + __popc(bal & ((1u << l) - 1u));
        if (m) cidx[base + pos] = idx[base + k];
        c += __popc(bal);
    }
    if (l == 0) cnt[b] = c;
}

// ---------------------------------------------------------------------------
// GEMM body: tf32 tensor-core GEMM  C = act(A @ W + bias) [+ addk]
// cp.async double-buffered staging (A and W already tf32-valued).
// 256 threads = 8 warps as 4(m) x 2(n); BN=64; frag mapping identical to the
// proven Round-8 kernel. ROUND: store outputs tf32-rounded (pre-rounding for
// the next layer's mma -- mathematically identical to staging-side cvt).
// ---------------------------------------------------------------------------
template <int BM_, int BK_, bool RELU, bool ADDK, bool ROUND>
__device__ __forceinline__ void gemm_body(
    float* smem, int bxn, int bym,
    const float* __restrict__ A, const float* __restrict__ W,
    const float* __restrict__ bias, const float* __restrict__ addk,
    float* __restrict__ C, int M, int N, int K)
{
    constexpr int BN_ = 64;
    constexpr int ALD = BK_ + 4;
    constexpr int BLD = BN_ + 4;
    constexpr int MT  = BM_ / 64;
    constexpr int A_PT = (BM_ * BK_ / 4) / 256;
    constexpr int B_PT = (BK_ * BN_ / 4) / 256;
    constexpr int ACOLS4 = BK_ / 4;
    constexpr int ASZ = BM_ * ALD;
    constexpr int BSZ = BK_ * BLD;

    float* As = smem;              // [2][ASZ]
    float* Bs = smem + 2 * ASZ;    // [2][BSZ]

    int tid = threadIdx.x;
    int m0 = bym * BM_;
    int n0 = bxn * BN_;

    // global->smem load mappings
    int a_off[A_PT];
    const float* Ap[A_PT];
    #pragma unroll
    for (int t = 0; t < A_PT; t++) {
        int id = tid + t * 256;
        int ar = id / ACOLS4, ac = (id % ACOLS4) * 4;
        a_off[t] = ar * ALD + ac;
        Ap[t] = A + (long)(m0 + ar) * K + ac;
    }
    int b_off[B_PT];
    const float* Bp[B_PT];
    #pragma unroll
    for (int t = 0; t < B_PT; t++) {
        int id = tid + t * 256;
        int br = id >> 4, bc = (id & 15) * 4;
        b_off[t] = br * BLD + bc;
        Bp[t] = W + (long)br * N + n0 + bc;
    }

    // warp / fragment coordinates
    int wid = tid >> 5;
    int lane = tid & 31;
    int g  = lane >> 2;
    int tg = lane & 3;
    int wm = wid & 3;
    int wn = wid >> 2;
    int wmb = wm * (BM_ / 4);
    int wnb = wn * 32;

    float acc[MT][4][4];
    #pragma unroll
    for (int mt = 0; mt < MT; mt++)
        #pragma unroll
        for (int nt = 0; nt < 4; nt++)
            #pragma unroll
            for (int r = 0; r < 4; r++) acc[mt][nt][r] = 0.f;

    // preload stage 0
    #pragma unroll
    for (int t = 0; t < A_PT; t++) { cp16(&As[a_off[t]], Ap[t]); Ap[t] += BK_; }
    #pragma unroll
    for (int t = 0; t < B_PT; t++) { cp16(&Bs[b_off[t]], Bp[t]); Bp[t] += (long)BK_ * N; }
    cp_commit();

    int nchunks = K / BK_;
    for (int kt = 0; kt < nchunks; kt++) {
        int cur = kt & 1;
        bool more = (kt + 1 < nchunks);
        cp_wait0();
        __syncthreads();
        if (more) {
            int nxt = cur ^ 1;
            #pragma unroll
            for (int t = 0; t < A_PT; t++) { cp16(&As[nxt * ASZ + a_off[t]], Ap[t]); Ap[t] += BK_; }
            #pragma unroll
            for (int t = 0; t < B_PT; t++) { cp16(&Bs[nxt * BSZ + b_off[t]], Bp[t]); Bp[t] += (long)BK_ * N; }
            cp_commit();
        }

        const float* Asc = As + cur * ASZ;
        const float* Bsc = Bs + cur * BSZ;
        #pragma unroll
        for (int ks = 0; ks < BK_; ks += 8) {
            uint32_t af[MT][4];
            #pragma unroll
            for (int mt = 0; mt < MT; mt++) {
                const float* ap = &Asc[(wmb + mt * 16 + g) * ALD + ks + tg];
                af[mt][0] = __float_as_uint(ap[0]);
                af[mt][1] = __float_as_uint(ap[8 * ALD]);
                af[mt][2] = __float_as_uint(ap[4]);
                af[mt][3] = __float_as_uint(ap[8 * ALD + 4]);
            }
            uint32_t bf[4][2];
            #pragma unroll
            for (int nt = 0; nt < 4; nt++) {
                const float* bp = &Bsc[(ks + tg) * BLD + wnb + nt * 8 + g];
                bf[nt][0] = __float_as_uint(bp[0]);
                bf[nt][1] = __float_as_uint(bp[4 * BLD]);
            }
            #pragma unroll
            for (int mt = 0; mt < MT; mt++)
                #pragma unroll
                for (int nt = 0; nt < 4; nt++)
                    mma_tf32(acc[mt][nt], af[mt], bf[nt]);
        }
        __syncthreads();
    }

    // epilogue (exact fp32; optional tf32 rounding of stored outputs)
    #pragma unroll
    for (int nt = 0; nt < 4; nt++) {
        int col = n0 + wnb + nt * 8 + tg * 2;
        float2 bs2 = *(const float2*)&bias[col];
        #pragma unroll
        for (int mt = 0; mt < MT; mt++) {
            int r0 = m0 + wmb + mt * 16 + g;
            int r1 = r0 + 8;
            float v00 = acc[mt][nt][0] + bs2.x;
            float v01 = acc[mt][nt][1] + bs2.y;
            float v10 = acc[mt][nt][2] + bs2.x;
            float v11 = acc[mt][nt][3] + bs2.y;
            if (RELU) {
                v00 = fmaxf(v00, 0.f); v01 = fmaxf(v01, 0.f);
                v10 = fmaxf(v10, 0.f); v11 = fmaxf(v11, 0.f);
            }
            if (ADDK) {
                float2 k0 = *(const float2*)&addk[(long)r0 * N + col];
                float2 k1 = *(const float2*)&addk[(long)r1 * N + col];
                v00 += k0.x; v01 += k0.y; v10 += k1.x; v11 += k1.y;
            }
            if (ROUND) {
                v00 = to_tf32(v00); v01 = to_tf32(v01);
                v10 = to_tf32(v10); v11 = to_tf32(v11);
            }
            *(float2*)&C[(long)r0 * N + col] = make_float2(v00, v01);
            *(float2*)&C[(long)r1 * N + col] = make_float2(v10, v11);
        }
    }
}

// ---------------------------------------------------------------------------
// Knowledge body (256 threads, 4 warp-PAIRS, one batch per pair).
//   knowledge[b][c] = sum_j relu( kg[cidx[b][j]] . Wkg[:,c] + bkg[c] )
// Wkg staged once/block as tf32 [k][n] (LD=68). Pair (warps 2p,2p+1) shares
// a 16-row gathered-chunk slot: warp h gathers rows r%2==h, then computes
// n8-tiles for cols h*32..h*32+31. Pair-scoped named barrier (bar.sync 1+p,
// 64) -- differing cnt[b] across pairs cannot deadlock. Masked row accum,
// warp-local shfl reduction over g, direct stores.
// ---------------------------------------------------------------------------
__device__ __forceinline__ void knowledge_body(
    float* smem, int kb,
    const float* __restrict__ kg, const float* __restrict__ Wkg,
    const float* __restrict__ bkg, const int* __restrict__ cidx,
    const int* __restrict__ cnt, float* __restrict__ know)
{
    float* Ws = smem;                // [64*68] tf32 Wkg [k][n]
    float* Ag = smem + KG_DIM * 68;  // [4][16*68]

    int tid = threadIdx.x;
    for (int i = tid * 4; i < KG_DIM * CC; i += 256 * 4) {
        int k = i >> 6, c = i & 63;
        *(float4*)&Ws[k * 68 + c] = cvt4(*(const float4*)&Wkg[i]);
    }
    __syncthreads();

    int w = tid >> 5, l = tid & 31;
    int pair = w >> 1, h = w & 1;
    int g = l >> 2, tg = l & 3;
    int b = kb * 4 + pair;
    float* Agp = Ag + pair * 16 * 68;
    int barid = 1 + pair;

    float bf[4][2];
    #pragma unroll
    for (int n8 = 0; n8 < 4; n8++) {
        float2 t = *(const float2*)&bkg[h * 32 + n8 * 8 + 2 * tg];
        bf[n8][0] = t.x; bf[n8][1] = t.y;
    }

    int n = cnt[b];
    const int* cp = cidx + b * K_SZ;

    float cs[4][2];
    #pragma unroll
    for (int n8 = 0; n8 < 4; n8++) { cs[n8][0] = 0.f; cs[n8][1] = 0.f; }

    for (int c0 = 0; c0 < n; c0 += 16) {
        int nr = min(16, n - c0);
        for (int r = h; r < nr; r += 2) {
            int row = cp[c0 + r];
            float2 g2 = *(const float2*)(kg + (long)row * KG_DIM + 2 * l);
            *(float2*)&Agp[r * 68 + 2 * l] = make_float2(to_tf32(g2.x), to_tf32(g2.y));
        }
        asm volatile("bar.sync %0, 64;" :: "r"(barid) : "memory");

        float acc[4][4];
        #pragma unroll
        for (int n8 = 0; n8 < 4; n8++)
            #pragma unroll
            for (int r = 0; r < 4; r++) acc[n8][r] = 0.f;

        #pragma unroll
        for (int ks = 0; ks < KG_DIM; ks += 8) {
            uint32_t af[4];
            const float* ap = &Agp[g * 68 + ks + tg];
            af[0] = __float_as_uint(ap[0]);
            af[1] = __float_as_uint(ap[8 * 68]);
            af[2] = __float_as_uint(ap[4]);
            af[3] = __float_as_uint(ap[8 * 68 + 4]);
            #pragma unroll
            for (int n8 = 0; n8 < 4; n8++) {
                uint32_t bfr[2];
                const float* bp = &Ws[(ks + tg) * 68 + h * 32 + n8 * 8 + g];
                bfr[0] = __float_as_uint(bp[0]);
                bfr[1] = __float_as_uint(bp[4 * 68]);
                mma_tf32(acc[n8], af, bfr);
            }
        }

        bool v0 = (g < nr);
        bool v1 = (g + 8 < nr);
        #pragma unroll
        for (int n8 = 0; n8 < 4; n8++) {
            if (v0) {
                cs[n8][0] += fmaxf(acc[n8][0] + bf[n8][0], 0.f);
                cs[n8][1] += fmaxf(acc[n8][1] + bf[n8][1], 0.f);
            }
            if (v1) {
                cs[n8][0] += fmaxf(acc[n8][2] + bf[n8][0], 0.f);
                cs[n8][1] += fmaxf(acc[n8][3] + bf[n8][1], 0.f);
            }
        }
        asm volatile("bar.sync %0, 64;" :: "r"(barid) : "memory");
    }

    #pragma unroll
    for (int n8 = 0; n8 < 4; n8++)
        #pragma unroll
        for (int j = 0; j < 2; j++) {
            float v = cs[n8][j];
            v += __shfl_xor_sync(0xffffffffu, v, 4);
            v += __shfl_xor_sync(0xffffffffu, v, 8);
            v += __shfl_xor_sync(0xffffffffu, v, 16);
            cs[n8][j] = v;
        }

    if (g < 4) {
        float o0 = 0.f, o1 = 0.f;
        #pragma unroll
        for (int n8 = 0; n8 < 4; n8++)
            if (n8 == g) { o0 = cs[n8][0]; o1 = cs[n8][1]; }
        *(float2*)&know[(long)b * CC + h * 32 + g * 8 + 2 * tg] = make_float2(o0, o1);
    }
}

// ---------------------------------------------------------------------------
// Fused kernel: L1a GEMM blocks (0..255) + knowledge blocks (256..2303).
// Union static smem: max(gemm 8960, knowledge 8704) floats = 35.8 KB.
// ---------------------------------------------------------------------------
#define L1A_BLOCKS 256
__global__ void __launch_bounds__(256) fused_l1a_know_kernel(
    const float* __restrict__ xt, const float* __restrict__ w1a,
    const float* __restrict__ b1a, float* __restrict__ h1,
    const float* __restrict__ kg, const float* __restrict__ Wkg,
    const float* __restrict__ bkg, const int* __restrict__ cidx,
    const int* __restrict__ cnt, float* __restrict__ know)
{
    __shared__ __align__(16) float smem[8960];
    if (blockIdx.x < L1A_BLOCKS) {
        gemm_body<64, 32, true, false, true>(
            smem, blockIdx.x & 1, blockIdx.x >> 1,
            xt, w1a, b1a, nullptr, h1, B_SZ, 128, IN_SZ);
    } else {
        knowledge_body(smem, blockIdx.x - L1A_BLOCKS, kg, Wkg, bkg, cidx, cnt, know);
    }
}

// ---------------------------------------------------------------------------
// Standalone GEMM kernel wrapper
// ---------------------------------------------------------------------------
template <int BM_, int BK_, bool RELU, bool ADDK, bool ROUND>
__global__ void __launch_bounds__(256) tgemm2_kernel(
    const float* __restrict__ A, const float* __restrict__ W,
    const float* __restrict__ bias, const float* __restrict__ addk,
    float* __restrict__ C, int M, int N, int K)
{
    constexpr int SM_FLOATS = 2 * BM_ * (BK_ + 4) + 2 * BK_ * 68;
    __shared__ __align__(16) float smem[SM_FLOATS];
    gemm_body<BM_, BK_, RELU, ADDK, ROUND>(
        smem, blockIdx.x, blockIdx.y, A, W, bias, addk, C, M, N, K);
}

// ---------------------------------------------------------------------------
// Launcher
// Input order (metadata): x, kg, idx, mask, Wkg, bkg, W1a,b1a, W1b,b1b,
//                         W1c,b1c, W1d,b1d, W2,b2.  Output: float [8192,1024].
// ---------------------------------------------------------------------------
extern "C" void kernel_launch(void* const* d_in, const int* in_sizes, int n_in,
                              void* d_out, int out_size)
{
    const float* x    = (const float*)d_in[0];
    const float* kg   = (const float*)d_in[1];
    const int*   idx  = (const int*)  d_in[2];
    const int*   mask = (const int*)  d_in[3];
    const float* Wkg  = (const float*)d_in[4];
    const float* bkg  = (const float*)d_in[5];
    const float* W1a  = (const float*)d_in[6];
    const float* b1a  = (const float*)d_in[7];
    const float* W1b  = (const float*)d_in[8];
    const float* b1b  = (const float*)d_in[9];
    const float* W1c  = (const float*)d_in[10];
    const float* b1c  = (const float*)d_in[11];
    const float* W1d  = (const float*)d_in[12];
    const float* b1d  = (const float*)d_in[13];
    const float* W2   = (const float*)d_in[14];
    const float* b2   = (const float*)d_in[15];
    float* out = (float*)d_out;

    float *h1, *h2, *h3, *h4, *know, *xt, *wt;
    int *cnt, *cidx;
    cudaGetSymbolAddress((void**)&h1,   g_h1);
    cudaGetSymbolAddress((void**)&h2,   g_h2);
    cudaGetSymbolAddress((void**)&h3,   g_h3);
    cudaGetSymbolAddress((void**)&h4,   g_h4);
    cudaGetSymbolAddress((void**)&know, g_know);
    cudaGetSymbolAddress((void**)&xt,   g_xt);
    cudaGetSymbolAddress((void**)&wt,   g_wt);
    cudaGetSymbolAddress((void**)&cnt,  g_cnt);
    cudaGetSymbolAddress((void**)&cidx, g_cidx);

    // 0) round x + weights to tf32 once   (1116160 float4s / 256 = 4360 blocks)
    preconvert_kernel<<<4360, 256>>>(x, W1a, W1b, W1c, W1d, W2);
    // 1) mask compaction
    compact_kernel<<<B_SZ / 8, 256>>>(idx, mask, cidx, cnt);
    // 2) fused: L1a GEMM (256 blocks) || knowledge branch (2048 blocks)
    fused_l1a_know_kernel<<<L1A_BLOCKS + B_SZ / 4, 256>>>(
        xt, wt + W1A_OFF, b1a, h1, kg, Wkg, bkg, cidx, cnt, know);
    // 3) L1b: [8192,128] @ [128,512]  BM=64,BK=32 -> 1024 blocks (proven config)
    tgemm2_kernel<64, 32, true, false, true><<<dim3(512 / 64, B_SZ / 64), 256>>>(
        h1, wt + W1B_OFF, b1b, nullptr, h2, B_SZ, 512, 128);
    // 4) L1c: [8192,512] @ [512,128]  BM=64,BK=32 (unchanged from Round 9)
    tgemm2_kernel<64, 32, true, false, true><<<dim3(128 / 64, B_SZ / 64), 256>>>(
        h2, wt + W1C_OFF, b1c, nullptr, h3, B_SZ, 128, 512);
    // 5) L1d: [8192,128] @ [128,64] + knowledge (unchanged from Round 9)
    tgemm2_kernel<64, 32, true, true, true><<<dim3(CC / 64, B_SZ / 64), 256>>>(
        h3, wt + W1D_OFF, b1d, know, h4, B_SZ, CC, 128);
    // 6) L2: [8192,64] @ [64,1024]  BM=64,BK=32 -> 2048 blocks (fp32 out)
    tgemm2_kernel<64, 32, false, false, false><<<dim3(OUT_SZ / 64, B_SZ / 64), 256>>>(
        h4, wt + W2_OFF, b2, nullptr, out, B_SZ, OUT_SZ, CC);
}

// round 13
// speedup vs baseline: 1.0764x; 1.0764x over previous
#include <cuda_runtime.h>
#include <cuda_bf16.h>
#include <cstdint>

// Shapes (fixed per reference)
#define B_SZ     8192
#define K_SZ     50
#define KG_DIM   64
#define IN_SZ    512
#define CC       64
#define OUT_SZ   1024

// ---------------------------------------------------------------------------
// Scratch (static device globals -- no runtime allocation allowed)
// ---------------------------------------------------------------------------
__device__ __align__(16) float g_h1[B_SZ * 128];
__device__ __align__(16) float g_h2[B_SZ * 512];
__device__ __align__(16) float g_h3[B_SZ * 128];
__device__ __align__(16) float g_h4[B_SZ * CC];
__device__ __align__(16) float g_know[B_SZ * CC];
__device__ __align__(16) float g_xt[B_SZ * IN_SZ];   // tf32-rounded x
__device__ __align__(16) float g_wt[270336];         // tf32-rounded weights (packed)
__device__ int   g_cnt[B_SZ];
__device__ int   g_cidx[B_SZ * K_SZ];

// packed weight offsets (floats)
#define W1A_OFF 0
#define W1B_OFF 65536
#define W1C_OFF 131072
#define W1D_OFF 196608
#define W2_OFF  204800

// ---------------------------------------------------------------------------
// tf32 / mma / cp.async helpers
// ---------------------------------------------------------------------------
__device__ __forceinline__ float to_tf32(float x) {
    uint32_t u;
    asm("cvt.rna.tf32.f32 %0, %1;" : "=r"(u) : "f"(x));
    return __uint_as_float(u);
}
__device__ __forceinline__ float4 cvt4(float4 v) {
    return make_float4(to_tf32(v.x), to_tf32(v.y), to_tf32(v.z), to_tf32(v.w));
}
__device__ __forceinline__ void mma_tf32(float* d, const uint32_t* a, const uint32_t* b) {
    asm volatile(
        "mma.sync.aligned.m16n8k8.row.col.f32.tf32.tf32.f32 "
        "{%0,%1,%2,%3}, {%4,%5,%6,%7}, {%8,%9}, {%0,%1,%2,%3};"
        : "+f"(d[0]), "+f"(d[1]), "+f"(d[2]), "+f"(d[3])
        : "r"(a[0]), "r"(a[1]), "r"(a[2]), "r"(a[3]), "r"(b[0]), "r"(b[1]));
}
__device__ __forceinline__ void cp16(void* smem_dst, const void* gsrc) {
    unsigned s = (unsigned)__cvta_generic_to_shared(smem_dst);
    asm volatile("cp.async.ca.shared.global [%0], [%1], 16;" :: "r"(s), "l"(gsrc));
}
__device__ __forceinline__ void cp_commit() { asm volatile("cp.async.commit_group;"); }
template <int N>
__device__ __forceinline__ void cp_wait() {
    asm volatile("cp.async.wait_group %0;" :: "n"(N));
}

// ---------------------------------------------------------------------------
// Kernel 0: preconvert x and all weights to tf32 (rna) once.
// ---------------------------------------------------------------------------
__global__ void __launch_bounds__(256) preconvert_kernel(
    const float* __restrict__ x,
    const float* __restrict__ W1a, const float* __restrict__ W1b,
    const float* __restrict__ W1c, const float* __restrict__ W1d,
    const float* __restrict__ W2)
{
    const int XT_F4 = (B_SZ * IN_SZ) / 4;   // 1048576
    int i4 = blockIdx.x * 256 + threadIdx.x;
    if (i4 < XT_F4) {
        ((float4*)g_xt)[i4] = cvt4(((const float4*)x)[i4]);
        return;
    }
    int j = i4 - XT_F4;
    const float* src; int dst;
    if      (j < 16384) { src = W1a; dst = W1A_OFF / 4; }
    else if (j < 32768) { src = W1b; dst = W1B_OFF / 4; j -= 16384; }
    else if (j < 49152) { src = W1c; dst = W1C_OFF / 4; j -= 32768; }
    else if (j < 51200) { src = W1d; dst = W1D_OFF / 4; j -= 49152; }
    else                { src = W2;  dst = W2_OFF  / 4; j -= 51200; }
    ((float4*)g_wt)[dst + j] = cvt4(((const float4*)src)[j]);
}

// ---------------------------------------------------------------------------
// Kernel 1: warp-per-row compaction of masked gather indices.
// ---------------------------------------------------------------------------
__global__ void __launch_bounds__(256) compact_kernel(
    const int* __restrict__ idx, const int* __restrict__ mask,
    int* __restrict__ cidx, int* __restrict__ cnt)
{
    int b = blockIdx.x * (blockDim.x >> 5) + (threadIdx.x >> 5);
    if (b >= B_SZ) return;
    int l = threadIdx.x & 31;
    int base = b * K_SZ;
    int c = 0;
    #pragma unroll
    for (int k0 = 0; k0 < K_SZ; k0 += 32) {
        int k = k0 + l;
        bool m = (k < K_SZ) && (mask[base + k] != 0);
        unsigned bal = __ballot_sync(0xffffffffu, m);
        int pos = c + __popc(bal & ((1u << l) - 1u));
        if (m) cidx[base + pos] = idx[base + k];
        c += __popc(bal);
    }
    if (l == 0) cnt[b] = c;
}

// ---------------------------------------------------------------------------
// GEMM body: tf32 tensor-core GEMM  C = act(A @ W + bias) [+ addk]
// Multi-stage cp.async ring (STAGES buffers). Canonical pattern:
//   prologue: issue chunks 0..STAGES-2, one commit group each
//   iter kt : wait_group<STAGES-2> (group kt complete; in-order), sync,
//             issue chunk kt+STAGES-1 (ALWAYS commit, empty at tail),
//             compute buffer kt%STAGES.
// Buffer-reuse hazard: chunk kt+STAGES-1 lands in buffer (kt-1)%STAGES,
// whose compute finished at iter kt-1 and is fenced by this iter's sync.
// 256 threads = 8 warps as 4(m) x 2(n); BN=64; frag mapping = Round-8 proven.
// ---------------------------------------------------------------------------
template <int BM_, int BK_, int STAGES, bool RELU, bool ADDK, bool ROUND>
__device__ __forceinline__ void gemm_body(
    float* smem, int bxn, int bym,
    const float* __restrict__ A, const float* __restrict__ W,
    const float* __restrict__ bias, const float* __restrict__ addk,
    float* __restrict__ C, int M, int N, int K)
{
    constexpr int BN_ = 64;
    constexpr int ALD = BK_ + 4;
    constexpr int BLD = BN_ + 4;
    constexpr int MT  = BM_ / 64;
    constexpr int A_PT = (BM_ * BK_ / 4) / 256;
    constexpr int B_PT = (BK_ * BN_ / 4) / 256;
    constexpr int ACOLS4 = BK_ / 4;
    constexpr int ASZ = BM_ * ALD;
    constexpr int BSZ = BK_ * BLD;

    float* As = smem;                   // [STAGES][ASZ]
    float* Bs = smem + STAGES * ASZ;    // [STAGES][BSZ]

    int tid = threadIdx.x;
    int m0 = bym * BM_;
    int n0 = bxn * BN_;

    // global->smem load mappings
    int a_off[A_PT];
    const float* Ap[A_PT];
    #pragma unroll
    for (int t = 0; t < A_PT; t++) {
        int id = tid + t * 256;
        int ar = id / ACOLS4, ac = (id % ACOLS4) * 4;
        a_off[t] = ar * ALD + ac;
        Ap[t] = A + (long)(m0 + ar) * K + ac;
    }
    int b_off[B_PT];
    const float* Bp[B_PT];
    #pragma unroll
    for (int t = 0; t < B_PT; t++) {
        int id = tid + t * 256;
        int br = id >> 4, bc = (id & 15) * 4;
        b_off[t] = br * BLD + bc;
        Bp[t] = W + (long)br * N + n0 + bc;
    }

    // warp / fragment coordinates
    int wid = tid >> 5;
    int lane = tid & 31;
    int g  = lane >> 2;
    int tg = lane & 3;
    int wm = wid & 3;
    int wn = wid >> 2;
    int wmb = wm * (BM_ / 4);
    int wnb = wn * 32;

    float acc[MT][4][4];
    #pragma unroll
    for (int mt = 0; mt < MT; mt++)
        #pragma unroll
        for (int nt = 0; nt < 4; nt++)
            #pragma unroll
            for (int r = 0; r < 4; r++) acc[mt][nt][r] = 0.f;

    int nchunks = K / BK_;

    // prologue: stages 0..STAGES-2
    #pragma unroll
    for (int s = 0; s < STAGES - 1; s++) {
        if (s < nchunks) {
            #pragma unroll
            for (int t = 0; t < A_PT; t++) { cp16(&As[s * ASZ + a_off[t]], Ap[t]); Ap[t] += BK_; }
            #pragma unroll
            for (int t = 0; t < B_PT; t++) { cp16(&Bs[s * BSZ + b_off[t]], Bp[t]); Bp[t] += (long)BK_ * N; }
        }
        cp_commit();
    }

    for (int kt = 0; kt < nchunks; kt++) {
        cp_wait<STAGES - 2>();
        __syncthreads();

        int pf = kt + STAGES - 1;
        if (pf < nchunks) {
            int pb = pf % STAGES;
            #pragma unroll
            for (int t = 0; t < A_PT; t++) { cp16(&As[pb * ASZ + a_off[t]], Ap[t]); Ap[t] += BK_; }
            #pragma unroll
            for (int t = 0; t < B_PT; t++) { cp16(&Bs[pb * BSZ + b_off[t]], Bp[t]); Bp[t] += (long)BK_ * N; }
        }
        cp_commit();   // always commit (empty groups at tail keep the count advancing)

        const float* Asc = As + (kt % STAGES) * ASZ;
        const float* Bsc = Bs + (kt % STAGES) * BSZ;
        #pragma unroll
        for (int ks = 0; ks < BK_; ks += 8) {
            uint32_t af[MT][4];
            #pragma unroll
            for (int mt = 0; mt < MT; mt++) {
                const float* ap = &Asc[(wmb + mt * 16 + g) * ALD + ks + tg];
                af[mt][0] = __float_as_uint(ap[0]);
                af[mt][1] = __float_as_uint(ap[8 * ALD]);
                af[mt][2] = __float_as_uint(ap[4]);
                af[mt][3] = __float_as_uint(ap[8 * ALD + 4]);
            }
            uint32_t bf[4][2];
            #pragma unroll
            for (int nt = 0; nt < 4; nt++) {
                const float* bp = &Bsc[(ks + tg) * BLD + wnb + nt * 8 + g];
                bf[nt][0] = __float_as_uint(bp[0]);
                bf[nt][1] = __float_as_uint(bp[4 * BLD]);
            }
            #pragma unroll
            for (int mt = 0; mt < MT; mt++)
                #pragma unroll
                for (int nt = 0; nt < 4; nt++)
                    mma_tf32(acc[mt][nt], af[mt], bf[nt]);
        }
    }

    // epilogue (exact fp32; optional tf32 rounding of stored outputs)
    #pragma unroll
    for (int nt = 0; nt < 4; nt++) {
        int col = n0 + wnb + nt * 8 + tg * 2;
        float2 bs2 = *(const float2*)&bias[col];
        #pragma unroll
        for (int mt = 0; mt < MT; mt++) {
            int r0 = m0 + wmb + mt * 16 + g;
            int r1 = r0 + 8;
            float v00 = acc[mt][nt][0] + bs2.x;
            float v01 = acc[mt][nt][1] + bs2.y;
            float v10 = acc[mt][nt][2] + bs2.x;
            float v11 = acc[mt][nt][3] + bs2.y;
            if (RELU) {
                v00 = fmaxf(v00, 0.f); v01 = fmaxf(v01, 0.f);
                v10 = fmaxf(v10, 0.f); v11 = fmaxf(v11, 0.f);
            }
            if (ADDK) {
                float2 k0 = *(const float2*)&addk[(long)r0 * N + col];
                float2 k1 = *(const float2*)&addk[(long)r1 * N + col];
                v00 += k0.x; v01 += k0.y; v10 += k1.x; v11 += k1.y;
            }
            if (ROUND) {
                v00 = to_tf32(v00); v01 = to_tf32(v01);
                v10 = to_tf32(v10); v11 = to_tf32(v11);
            }
            *(float2*)&C[(long)r0 * N + col] = make_float2(v00, v01);
            *(float2*)&C[(long)r1 * N + col] = make_float2(v10, v11);
        }
    }
}

// ---------------------------------------------------------------------------
// Knowledge body (256 threads, 4 warp-PAIRS, one batch per pair) -- unchanged
// from the proven Round-9 version.
// ---------------------------------------------------------------------------
__device__ __forceinline__ void knowledge_body(
    float* smem, int kb,
    const float* __restrict__ kg, const float* __restrict__ Wkg,
    const float* __restrict__ bkg, const int* __restrict__ cidx,
    const int* __restrict__ cnt, float* __restrict__ know)
{
    float* Ws = smem;                // [64*68] tf32 Wkg [k][n]
    float* Ag = smem + KG_DIM * 68;  // [4][16*68]

    int tid = threadIdx.x;
    for (int i = tid * 4; i < KG_DIM * CC; i += 256 * 4) {
        int k = i >> 6, c = i & 63;
        *(float4*)&Ws[k * 68 + c] = cvt4(*(const float4*)&Wkg[i]);
    }
    __syncthreads();

    int w = tid >> 5, l = tid & 31;
    int pair = w >> 1, h = w & 1;
    int g = l >> 2, tg = l & 3;
    int b = kb * 4 + pair;
    float* Agp = Ag + pair * 16 * 68;
    int barid = 1 + pair;

    float bf[4][2];
    #pragma unroll
    for (int n8 = 0; n8 < 4; n8++) {
        float2 t = *(const float2*)&bkg[h * 32 + n8 * 8 + 2 * tg];
        bf[n8][0] = t.x; bf[n8][1] = t.y;
    }

    int n = cnt[b];
    const int* cp = cidx + b * K_SZ;

    float cs[4][2];
    #pragma unroll
    for (int n8 = 0; n8 < 4; n8++) { cs[n8][0] = 0.f; cs[n8][1] = 0.f; }

    for (int c0 = 0; c0 < n; c0 += 16) {
        int nr = min(16, n - c0);
        for (int r = h; r < nr; r += 2) {
            int row = cp[c0 + r];
            float2 g2 = *(const float2*)(kg + (long)row * KG_DIM + 2 * l);
            *(float2*)&Agp[r * 68 + 2 * l] = make_float2(to_tf32(g2.x), to_tf32(g2.y));
        }
        asm volatile("bar.sync %0, 64;" :: "r"(barid) : "memory");

        float acc[4][4];
        #pragma unroll
        for (int n8 = 0; n8 < 4; n8++)
            #pragma unroll
            for (int r = 0; r < 4; r++) acc[n8][r] = 0.f;

        #pragma unroll
        for (int ks = 0; ks < KG_DIM; ks += 8) {
            uint32_t af[4];
            const float* ap = &Agp[g * 68 + ks + tg];
            af[0] = __float_as_uint(ap[0]);
            af[1] = __float_as_uint(ap[8 * 68]);
            af[2] = __float_as_uint(ap[4]);
            af[3] = __float_as_uint(ap[8 * 68 + 4]);
            #pragma unroll
            for (int n8 = 0; n8 < 4; n8++) {
                uint32_t bfr[2];
                const float* bp = &Ws[(ks + tg) * 68 + h * 32 + n8 * 8 + g];
                bfr[0] = __float_as_uint(bp[0]);
                bfr[1] = __float_as_uint(bp[4 * 68]);
                mma_tf32(acc[n8], af, bfr);
            }
        }

        bool v0 = (g < nr);
        bool v1 = (g + 8 < nr);
        #pragma unroll
        for (int n8 = 0; n8 < 4; n8++) {
            if (v0) {
                cs[n8][0] += fmaxf(acc[n8][0] + bf[n8][0], 0.f);
                cs[n8][1] += fmaxf(acc[n8][1] + bf[n8][1], 0.f);
            }
            if (v1) {
                cs[n8][0] += fmaxf(acc[n8][2] + bf[n8][0], 0.f);
                cs[n8][1] += fmaxf(acc[n8][3] + bf[n8][1], 0.f);
            }
        }
        asm volatile("bar.sync %0, 64;" :: "r"(barid) : "memory");
    }

    #pragma unroll
    for (int n8 = 0; n8 < 4; n8++)
        #pragma unroll
        for (int j = 0; j < 2; j++) {
            float v = cs[n8][j];
            v += __shfl_xor_sync(0xffffffffu, v, 4);
            v += __shfl_xor_sync(0xffffffffu, v, 8);
            v += __shfl_xor_sync(0xffffffffu, v, 16);
            cs[n8][j] = v;
        }

    if (g < 4) {
        float o0 = 0.f, o1 = 0.f;
        #pragma unroll
        for (int n8 = 0; n8 < 4; n8++)
            if (n8 == g) { o0 = cs[n8][0]; o1 = cs[n8][1]; }
        *(float2*)&know[(long)b * CC + h * 32 + g * 8 + 2 * tg] = make_float2(o0, o1);
    }
}

// ---------------------------------------------------------------------------
// Fused kernel: L1a GEMM blocks (0..255, 2-stage) + knowledge (256..2303).
// Union static smem: max(gemm 8960, knowledge 8704) floats = 35.8 KB.
// ---------------------------------------------------------------------------
#define L1A_BLOCKS 256
__global__ void __launch_bounds__(256) fused_l1a_know_kernel(
    const float* __restrict__ xt, const float* __restrict__ w1a,
    const float* __restrict__ b1a, float* __restrict__ h1,
    const float* __restrict__ kg, const float* __restrict__ Wkg,
    const float* __restrict__ bkg, const int* __restrict__ cidx,
    const int* __restrict__ cnt, float* __restrict__ know)
{
    __shared__ __align__(16) float smem[8960];
    if (blockIdx.x < L1A_BLOCKS) {
        gemm_body<64, 32, 2, true, false, true>(
            smem, blockIdx.x & 1, blockIdx.x >> 1,
            xt, w1a, b1a, nullptr, h1, B_SZ, 128, IN_SZ);
    } else {
        knowledge_body(smem, blockIdx.x - L1A_BLOCKS, kg, Wkg, bkg, cidx, cnt, know);
    }
}

// ---------------------------------------------------------------------------
// Standalone GEMM kernel wrapper
// ---------------------------------------------------------------------------
template <int BM_, int BK_, int STAGES, bool RELU, bool ADDK, bool ROUND>
__global__ void __launch_bounds__(256) tgemm2_kernel(
    const float* __restrict__ A, const float* __restrict__ W,
    const float* __restrict__ bias, const float* __restrict__ addk,
    float* __restrict__ C, int M, int N, int K)
{
    constexpr int SM_FLOATS = STAGES * BM_ * (BK_ + 4) + STAGES * BK_ * 68;
    __shared__ __align__(16) float smem[SM_FLOATS];
    gemm_body<BM_, BK_, STAGES, RELU, ADDK, ROUND>(
        smem, blockIdx.x, blockIdx.y, A, W, bias, addk, C, M, N, K);
}

// ---------------------------------------------------------------------------
// Launcher
// Input order (metadata): x, kg, idx, mask, Wkg, bkg, W1a,b1a, W1b,b1b,
//                         W1c,b1c, W1d,b1d, W2,b2.  Output: float [8192,1024].
// ---------------------------------------------------------------------------
extern "C" void kernel_launch(void* const* d_in, const int* in_sizes, int n_in,
                              void* d_out, int out_size)
{
    const float* x    = (const float*)d_in[0];
    const float* kg   = (const float*)d_in[1];
    const int*   idx  = (const int*)  d_in[2];
    const int*   mask = (const int*)  d_in[3];
    const float* Wkg  = (const float*)d_in[4];
    const float* bkg  = (const float*)d_in[5];
    const float* W1a  = (const float*)d_in[6];
    const float* b1a  = (const float*)d_in[7];
    const float* W1b  = (const float*)d_in[8];
    const float* b1b  = (const float*)d_in[9];
    const float* W1c  = (const float*)d_in[10];
    const float* b1c  = (const float*)d_in[11];
    const float* W1d  = (const float*)d_in[12];
    const float* b1d  = (const float*)d_in[13];
    const float* W2   = (const float*)d_in[14];
    const float* b2   = (const float*)d_in[15];
    float* out = (float*)d_out;

    float *h1, *h2, *h3, *h4, *know, *xt, *wt;
    int *cnt, *cidx;
    cudaGetSymbolAddress((void**)&h1,   g_h1);
    cudaGetSymbolAddress((void**)&h2,   g_h2);
    cudaGetSymbolAddress((void**)&h3,   g_h3);
    cudaGetSymbolAddress((void**)&h4,   g_h4);
    cudaGetSymbolAddress((void**)&know, g_know);
    cudaGetSymbolAddress((void**)&xt,   g_xt);
    cudaGetSymbolAddress((void**)&wt,   g_wt);
    cudaGetSymbolAddress((void**)&cnt,  g_cnt);
    cudaGetSymbolAddress((void**)&cidx, g_cidx);

    // 0) round x + weights to tf32 once
    preconvert_kernel<<<4360, 256>>>(x, W1a, W1b, W1c, W1d, W2);
    // 1) mask compaction
    compact_kernel<<<B_SZ / 8, 256>>>(idx, mask, cidx, cnt);
    // 2) fused: L1a GEMM (256 blocks, 2-stage) || knowledge (2048 blocks)
    fused_l1a_know_kernel<<<L1A_BLOCKS + B_SZ / 4, 256>>>(
        xt, wt + W1A_OFF, b1a, h1, kg, Wkg, bkg, cidx, cnt, know);
    // 3) L1b: [8192,128] @ [128,512]  BM=128/BK=16, 3-stage pipeline
    tgemm2_kernel<128, 16, 3, true, false, true><<<dim3(512 / 64, B_SZ / 128), 256>>>(
        h1, wt + W1B_OFF, b1b, nullptr, h2, B_SZ, 512, 128);
    // 4) L1c: [8192,512] @ [512,128]  BM=64/BK=32, 2-stage (proven)
    tgemm2_kernel<64, 32, 2, true, false, true><<<dim3(128 / 64, B_SZ / 64), 256>>>(
        h2, wt + W1C_OFF, b1c, nullptr, h3, B_SZ, 128, 512);
    // 5) L1d: [8192,128] @ [128,64] + knowledge  BM=64/BK=32, 2-stage (proven)
    tgemm2_kernel<64, 32, 2, true, true, true><<<dim3(CC / 64, B_SZ / 64), 256>>>(
        h3, wt + W1D_OFF, b1d, know, h4, B_SZ, CC, 128);
    // 6) L2: [8192,64] @ [64,1024]  BM=128/BK=16, 3-stage (fp32 out)
    tgemm2_kernel<128, 16, 3, false, false, false><<<dim3(OUT_SZ / 64, B_SZ / 128), 256>>>(
        h4, wt + W2_OFF, b2, nullptr, out, B_SZ, OUT_SZ, CC);
}

// round 14
// speedup vs baseline: 1.1173x; 1.0380x over previous
#include <cuda_runtime.h>
#include <cuda_bf16.h>
#include <cstdint>

// Shapes (fixed per reference)
#define B_SZ     8192
#define K_SZ     50
#define KG_DIM   64
#define IN_SZ    512
#define CC       64
#define OUT_SZ   1024

// ---------------------------------------------------------------------------
// Scratch (static device globals -- no runtime allocation allowed)
// ---------------------------------------------------------------------------
__device__ __align__(16) float g_h1[B_SZ * 128];
__device__ __align__(16) float g_h2[B_SZ * 512];
__device__ __align__(16) float g_h3[B_SZ * 128];
__device__ __align__(16) float g_h4[B_SZ * CC];
__device__ __align__(16) float g_know[B_SZ * CC];
__device__ __align__(16) float g_wt[270336];   // tf32-rounded weights (packed)
__device__ int   g_cnt[B_SZ];
__device__ int   g_cidx[B_SZ * K_SZ];

// packed weight offsets (floats)
#define W1A_OFF 0
#define W1B_OFF 65536
#define W1C_OFF 131072
#define W1D_OFF 196608
#define W2_OFF  204800

// ---------------------------------------------------------------------------
// tf32 / mma / cp.async helpers
// ---------------------------------------------------------------------------
__device__ __forceinline__ float to_tf32(float x) {
    uint32_t u;
    asm("cvt.rna.tf32.f32 %0, %1;" : "=r"(u) : "f"(x));
    return __uint_as_float(u);
}
__device__ __forceinline__ float4 cvt4(float4 v) {
    return make_float4(to_tf32(v.x), to_tf32(v.y), to_tf32(v.z), to_tf32(v.w));
}
__device__ __forceinline__ void mma_tf32(float* d, const uint32_t* a, const uint32_t* b) {
    asm volatile(
        "mma.sync.aligned.m16n8k8.row.col.f32.tf32.tf32.f32 "
        "{%0,%1,%2,%3}, {%4,%5,%6,%7}, {%8,%9}, {%0,%1,%2,%3};"
        : "+f"(d[0]), "+f"(d[1]), "+f"(d[2]), "+f"(d[3])
        : "r"(a[0]), "r"(a[1]), "r"(a[2]), "r"(a[3]), "r"(b[0]), "r"(b[1]));
}
__device__ __forceinline__ void cp16(void* smem_dst, const void* gsrc) {
    unsigned s = (unsigned)__cvta_generic_to_shared(smem_dst);
    asm volatile("cp.async.ca.shared.global [%0], [%1], 16;" :: "r"(s), "l"(gsrc));
}
__device__ __forceinline__ void cp_commit() { asm volatile("cp.async.commit_group;"); }
template <int N>
__device__ __forceinline__ void cp_wait() {
    asm volatile("cp.async.wait_group %0;" :: "n"(N));
}

// ---------------------------------------------------------------------------
// Setup kernel: blocks 0..1023 = mask compaction (8 rows/block);
//               blocks 1024..1287 = weight tf32 preconvert (256 float4/block).
// ---------------------------------------------------------------------------
__global__ void __launch_bounds__(256) setup_kernel(
    const int* __restrict__ idx, const int* __restrict__ mask,
    int* __restrict__ cidx, int* __restrict__ cnt,
    const float* __restrict__ W1a, const float* __restrict__ W1b,
    const float* __restrict__ W1c, const float* __restrict__ W1d,
    const float* __restrict__ W2)
{
    if (blockIdx.x < 1024) {
        int b = blockIdx.x * 8 + (threadIdx.x >> 5);
        int l = threadIdx.x & 31;
        int base = b * K_SZ;
        int c = 0;
        #pragma unroll
        for (int k0 = 0; k0 < K_SZ; k0 += 32) {
            int k = k0 + l;
            bool m = (k < K_SZ) && (mask[base + k] != 0);
            unsigned bal = __ballot_sync(0xffffffffu, m);
            int pos = c + __popc(bal & ((1u << l) - 1u));
            if (m) cidx[base + pos] = idx[base + k];
            c += __popc(bal);
        }
        if (l == 0) cnt[b] = c;
        return;
    }
    int j = (blockIdx.x - 1024) * 256 + threadIdx.x;   // float4 index, < 67584
    if (j >= 67584) return;
    const float* src; int dst;
    if      (j < 16384) { src = W1a; dst = W1A_OFF / 4; }
    else if (j < 32768) { src = W1b; dst = W1B_OFF / 4; j -= 16384; }
    else if (j < 49152) { src = W1c; dst = W1C_OFF / 4; j -= 32768; }
    else if (j < 51200) { src = W1d; dst = W1D_OFF / 4; j -= 49152; }
    else                { src = W2;  dst = W2_OFF  / 4; j -= 51200; }
    ((float4*)g_wt)[dst + j] = cvt4(((const float4*)src)[j]);
}

// ---------------------------------------------------------------------------
// GEMM body: tf32 tensor-core GEMM  C = act(A @ W + bias) [+ addk]
// Multi-stage cp.async ring (STAGES buffers), canonical always-commit form.
// CVTA=true: A is raw fp32, staged via LDG -> cvt.rna -> STS with one-chunk
// register prefetch (issued after commit, overlapping compute). B always via
// cp.async (pre-rounded tf32). Hazards: STS to buffer pb=(kt-1)%STAGES at
// iter kt is safe (its readers finished at iter kt-1, fenced by this iter's
// __syncthreads); visibility to its reader at iter kt+STAGES-1 is fenced by
// the intervening syncs. 256 threads = 8 warps as 4(m) x 2(n); BN=64.
// ---------------------------------------------------------------------------
template <int BM_, int BK_, int STAGES, bool RELU, bool ADDK, bool ROUND, bool CVTA>
__device__ __forceinline__ void gemm_body(
    float* smem, int bxn, int bym,
    const float* __restrict__ A, const float* __restrict__ W,
    const float* __restrict__ bias, const float* __restrict__ addk,
    float* __restrict__ C, int M, int N, int K)
{
    constexpr int BN_ = 64;
    constexpr int ALD = BK_ + 4;
    constexpr int BLD = BN_ + 4;
    constexpr int MT  = BM_ / 64;
    constexpr int A_PT = (BM_ * BK_ / 4) / 256;
    constexpr int B_PT = (BK_ * BN_ / 4) / 256;
    constexpr int ACOLS4 = BK_ / 4;
    constexpr int ASZ = BM_ * ALD;
    constexpr int BSZ = BK_ * BLD;

    float* As = smem;                   // [STAGES][ASZ]
    float* Bs = smem + STAGES * ASZ;    // [STAGES][BSZ]

    int tid = threadIdx.x;
    int m0 = bym * BM_;
    int n0 = bxn * BN_;

    // global->smem load mappings
    int a_off[A_PT];
    const float* Ap[A_PT];
    #pragma unroll
    for (int t = 0; t < A_PT; t++) {
        int id = tid + t * 256;
        int ar = id / ACOLS4, ac = (id % ACOLS4) * 4;
        a_off[t] = ar * ALD + ac;
        Ap[t] = A + (long)(m0 + ar) * K + ac;
    }
    int b_off[B_PT];
    const float* Bp[B_PT];
    #pragma unroll
    for (int t = 0; t < B_PT; t++) {
        int id = tid + t * 256;
        int br = id >> 4, bc = (id & 15) * 4;
        b_off[t] = br * BLD + bc;
        Bp[t] = W + (long)br * N + n0 + bc;
    }

    // warp / fragment coordinates
    int wid = tid >> 5;
    int lane = tid & 31;
    int g  = lane >> 2;
    int tg = lane & 3;
    int wm = wid & 3;
    int wn = wid >> 2;
    int wmb = wm * (BM_ / 4);
    int wnb = wn * 32;

    float acc[MT][4][4];
    #pragma unroll
    for (int mt = 0; mt < MT; mt++)
        #pragma unroll
        for (int nt = 0; nt < 4; nt++)
            #pragma unroll
            for (int r = 0; r < 4; r++) acc[mt][nt][r] = 0.f;

    int nchunks = K / BK_;
    float4 pa[A_PT];   // CVTA register prefetch

    // prologue: stages 0..STAGES-2
    #pragma unroll
    for (int s = 0; s < STAGES - 1; s++) {
        if (s < nchunks) {
            if (CVTA) {
                #pragma unroll
                for (int t = 0; t < A_PT; t++) { pa[t] = *(const float4*)Ap[t]; Ap[t] += BK_; }
                #pragma unroll
                for (int t = 0; t < A_PT; t++) *(float4*)&As[s * ASZ + a_off[t]] = cvt4(pa[t]);
            } else {
                #pragma unroll
                for (int t = 0; t < A_PT; t++) { cp16(&As[s * ASZ + a_off[t]], Ap[t]); Ap[t] += BK_; }
            }
            #pragma unroll
            for (int t = 0; t < B_PT; t++) { cp16(&Bs[s * BSZ + b_off[t]], Bp[t]); Bp[t] += (long)BK_ * N; }
        }
        cp_commit();
    }
    if (CVTA && (STAGES - 1 < nchunks)) {
        #pragma unroll
        for (int t = 0; t < A_PT; t++) { pa[t] = *(const float4*)Ap[t]; Ap[t] += BK_; }
    }

    for (int kt = 0; kt < nchunks; kt++) {
        cp_wait<STAGES - 2>();
        __syncthreads();

        int pf = kt + STAGES - 1;
        if (pf < nchunks) {
            int pb = pf % STAGES;
            if (CVTA) {
                #pragma unroll
                for (int t = 0; t < A_PT; t++) *(float4*)&As[pb * ASZ + a_off[t]] = cvt4(pa[t]);
            } else {
                #pragma unroll
                for (int t = 0; t < A_PT; t++) { cp16(&As[pb * ASZ + a_off[t]], Ap[t]); Ap[t] += BK_; }
            }
            #pragma unroll
            for (int t = 0; t < B_PT; t++) { cp16(&Bs[pb * BSZ + b_off[t]], Bp[t]); Bp[t] += (long)BK_ * N; }
        }
        cp_commit();   // always commit (empty groups at tail keep the count advancing)

        if (CVTA && (pf + 1 < nchunks)) {   // prefetch next A chunk; overlaps compute
            #pragma unroll
            for (int t = 0; t < A_PT; t++) { pa[t] = *(const float4*)Ap[t]; Ap[t] += BK_; }
        }

        const float* Asc = As + (kt % STAGES) * ASZ;
        const float* Bsc = Bs + (kt % STAGES) * BSZ;
        #pragma unroll
        for (int ks = 0; ks < BK_; ks += 8) {
            uint32_t af[MT][4];
            #pragma unroll
            for (int mt = 0; mt < MT; mt++) {
                const float* ap = &Asc[(wmb + mt * 16 + g) * ALD + ks + tg];
                af[mt][0] = __float_as_uint(ap[0]);
                af[mt][1] = __float_as_uint(ap[8 * ALD]);
                af[mt][2] = __float_as_uint(ap[4]);
                af[mt][3] = __float_as_uint(ap[8 * ALD + 4]);
            }
            uint32_t bf[4][2];
            #pragma unroll
            for (int nt = 0; nt < 4; nt++) {
                const float* bp = &Bsc[(ks + tg) * BLD + wnb + nt * 8 + g];
                bf[nt][0] = __float_as_uint(bp[0]);
                bf[nt][1] = __float_as_uint(bp[4 * BLD]);
            }
            #pragma unroll
            for (int mt = 0; mt < MT; mt++)
                #pragma unroll
                for (int nt = 0; nt < 4; nt++)
                    mma_tf32(acc[mt][nt], af[mt], bf[nt]);
        }
    }

    // epilogue (exact fp32; optional tf32 rounding of stored outputs)
    #pragma unroll
    for (int nt = 0; nt < 4; nt++) {
        int col = n0 + wnb + nt * 8 + tg * 2;
        float2 bs2 = *(const float2*)&bias[col];
        #pragma unroll
        for (int mt = 0; mt < MT; mt++) {
            int r0 = m0 + wmb + mt * 16 + g;
            int r1 = r0 + 8;
            float v00 = acc[mt][nt][0] + bs2.x;
            float v01 = acc[mt][nt][1] + bs2.y;
            float v10 = acc[mt][nt][2] + bs2.x;
            float v11 = acc[mt][nt][3] + bs2.y;
            if (RELU) {
                v00 = fmaxf(v00, 0.f); v01 = fmaxf(v01, 0.f);
                v10 = fmaxf(v10, 0.f); v11 = fmaxf(v11, 0.f);
            }
            if (ADDK) {
                float2 k0 = *(const float2*)&addk[(long)r0 * N + col];
                float2 k1 = *(const float2*)&addk[(long)r1 * N + col];
                v00 += k0.x; v01 += k0.y; v10 += k1.x; v11 += k1.y;
            }
            if (ROUND) {
                v00 = to_tf32(v00); v01 = to_tf32(v01);
                v10 = to_tf32(v10); v11 = to_tf32(v11);
            }
            *(float2*)&C[(long)r0 * N + col] = make_float2(v00, v01);
            *(float2*)&C[(long)r1 * N + col] = make_float2(v10, v11);
        }
    }
}

// ---------------------------------------------------------------------------
// Knowledge body (256 threads, 4 warp-PAIRS, one batch per pair).
//   knowledge[b][c] = sum_j relu( kg[cidx[b][j]] . Wkg[:,c] + bkg[c] )
// v2: next-chunk gather rows are prefetched into REGISTERS right after the
// staging barrier, overlapping the ~500-cycle L2 gather chain with the 32-mma
// compute. Pair-scoped named barrier (bar.sync 1+p, 64); masked row accum;
// warp-local shfl reduction; store offset includes h*32 (R10 regression!).
// ---------------------------------------------------------------------------
__device__ __forceinline__ void knowledge_body(
    float* smem, int kb,
    const float* __restrict__ kg, const float* __restrict__ Wkg,
    const float* __restrict__ bkg, const int* __restrict__ cidx,
    const int* __restrict__ cnt, float* __restrict__ know)
{
    float* Ws = smem;                // [64*68] tf32 Wkg [k][n]
    float* Ag = smem + KG_DIM * 68;  // [4][16*68]

    int tid = threadIdx.x;
    for (int i = tid * 4; i < KG_DIM * CC; i += 256 * 4) {
        int k = i >> 6, c = i & 63;
        *(float4*)&Ws[k * 68 + c] = cvt4(*(const float4*)&Wkg[i]);
    }
    __syncthreads();

    int w = tid >> 5, l = tid & 31;
    int pair = w >> 1, h = w & 1;
    int g = l >> 2, tg = l & 3;
    int b = kb * 4 + pair;
    float* Agp = Ag + pair * 16 * 68;
    int barid = 1 + pair;

    float bf[4][2];
    #pragma unroll
    for (int n8 = 0; n8 < 4; n8++) {
        float2 t = *(const float2*)&bkg[h * 32 + n8 * 8 + 2 * tg];
        bf[n8][0] = t.x; bf[n8][1] = t.y;
    }

    int n = cnt[b];
    const int* cp = cidx + b * K_SZ;

    float cs[4][2];
    #pragma unroll
    for (int n8 = 0; n8 < 4; n8++) { cs[n8][0] = 0.f; cs[n8][1] = 0.f; }

    // prefetch chunk 0 rows (this warp gathers rows r%2==h)
    float2 pr[8];
    {
        int nr0 = min(16, n);
        #pragma unroll
        for (int i = 0; i < 8; i++) {
            int r = 2 * i + h;
            if (r < nr0) pr[i] = *(const float2*)(kg + (long)cp[r] * KG_DIM + 2 * l);
        }
    }

    for (int c0 = 0; c0 < n; c0 += 16) {
        int nr = min(16, n - c0);
        // stage current chunk from prefetch regs (tf32)
        #pragma unroll
        for (int i = 0; i < 8; i++) {
            int r = 2 * i + h;
            if (r < nr)
                *(float2*)&Agp[r * 68 + 2 * l] =
                    make_float2(to_tf32(pr[i].x), to_tf32(pr[i].y));
        }
        asm volatile("bar.sync %0, 64;" :: "r"(barid) : "memory");

        // prefetch NEXT chunk rows -- overlaps the mma below
        int c1 = c0 + 16;
        if (c1 < n) {
            int nrn = min(16, n - c1);
            #pragma unroll
            for (int i = 0; i < 8; i++) {
                int r = 2 * i + h;
                if (r < nrn) pr[i] = *(const float2*)(kg + (long)cp[c1 + r] * KG_DIM + 2 * l);
            }
        }

        float acc[4][4];
        #pragma unroll
        for (int n8 = 0; n8 < 4; n8++)
            #pragma unroll
            for (int r = 0; r < 4; r++) acc[n8][r] = 0.f;

        #pragma unroll
        for (int ks = 0; ks < KG_DIM; ks += 8) {
            uint32_t af[4];
            const float* ap = &Agp[g * 68 + ks + tg];
            af[0] = __float_as_uint(ap[0]);
            af[1] = __float_as_uint(ap[8 * 68]);
            af[2] = __float_as_uint(ap[4]);
            af[3] = __float_as_uint(ap[8 * 68 + 4]);
            #pragma unroll
            for (int n8 = 0; n8 < 4; n8++) {
                uint32_t bfr[2];
                const float* bp = &Ws[(ks + tg) * 68 + h * 32 + n8 * 8 + g];
                bfr[0] = __float_as_uint(bp[0]);
                bfr[1] = __float_as_uint(bp[4 * 68]);
                mma_tf32(acc[n8], af, bfr);
            }
        }

        bool v0 = (g < nr);
        bool v1 = (g + 8 < nr);
        #pragma unroll
        for (int n8 = 0; n8 < 4; n8++) {
            if (v0) {
                cs[n8][0] += fmaxf(acc[n8][0] + bf[n8][0], 0.f);
                cs[n8][1] += fmaxf(acc[n8][1] + bf[n8][1], 0.f);
            }
            if (v1) {
                cs[n8][0] += fmaxf(acc[n8][2] + bf[n8][0], 0.f);
                cs[n8][1] += fmaxf(acc[n8][3] + bf[n8][1], 0.f);
            }
        }
        asm volatile("bar.sync %0, 64;" :: "r"(barid) : "memory");
    }

    #pragma unroll
    for (int n8 = 0; n8 < 4; n8++)
        #pragma unroll
        for (int j = 0; j < 2; j++) {
            float v = cs[n8][j];
            v += __shfl_xor_sync(0xffffffffu, v, 4);
            v += __shfl_xor_sync(0xffffffffu, v, 8);
            v += __shfl_xor_sync(0xffffffffu, v, 16);
            cs[n8][j] = v;
        }

    if (g < 4) {
        float o0 = 0.f, o1 = 0.f;
        #pragma unroll
        for (int n8 = 0; n8 < 4; n8++)
            if (n8 == g) { o0 = cs[n8][0]; o1 = cs[n8][1]; }
        // NOTE: h*32 offset is load-bearing (Round-10 regression)
        *(float2*)&know[(long)b * CC + h * 32 + g * 8 + 2 * tg] = make_float2(o0, o1);
    }
}

// ---------------------------------------------------------------------------
// Fused kernel: L1a GEMM blocks (0..255, 2-stage, CVTA from raw x) +
//               knowledge blocks (256..2303).
// Union static smem: max(gemm 8960, knowledge 8704) floats = 35.8 KB.
// ---------------------------------------------------------------------------
#define L1A_BLOCKS 256
__global__ void __launch_bounds__(256) fused_l1a_know_kernel(
    const float* __restrict__ x, const float* __restrict__ w1a,
    const float* __restrict__ b1a, float* __restrict__ h1,
    const float* __restrict__ kg, const float* __restrict__ Wkg,
    const float* __restrict__ bkg, const int* __restrict__ cidx,
    const int* __restrict__ cnt, float* __restrict__ know)
{
    __shared__ __align__(16) float smem[8960];
    if (blockIdx.x < L1A_BLOCKS) {
        gemm_body<64, 32, 2, true, false, true, true>(
            smem, blockIdx.x & 1, blockIdx.x >> 1,
            x, w1a, b1a, nullptr, h1, B_SZ, 128, IN_SZ);
    } else {
        knowledge_body(smem, blockIdx.x - L1A_BLOCKS, kg, Wkg, bkg, cidx, cnt, know);
    }
}

// ---------------------------------------------------------------------------
// Standalone GEMM kernel wrapper
// ---------------------------------------------------------------------------
template <int BM_, int BK_, int STAGES, bool RELU, bool ADDK, bool ROUND>
__global__ void __launch_bounds__(256) tgemm2_kernel(
    const float* __restrict__ A, const float* __restrict__ W,
    const float* __restrict__ bias, const float* __restrict__ addk,
    float* __restrict__ C, int M, int N, int K)
{
    constexpr int SM_FLOATS = STAGES * BM_ * (BK_ + 4) + STAGES * BK_ * 68;
    __shared__ __align__(16) float smem[SM_FLOATS];
    gemm_body<BM_, BK_, STAGES, RELU, ADDK, ROUND, false>(
        smem, blockIdx.x, blockIdx.y, A, W, bias, addk, C, M, N, K);
}

// ---------------------------------------------------------------------------
// Launcher
// Input order (metadata): x, kg, idx, mask, Wkg, bkg, W1a,b1a, W1b,b1b,
//                         W1c,b1c, W1d,b1d, W2,b2.  Output: float [8192,1024].
// ---------------------------------------------------------------------------
extern "C" void kernel_launch(void* const* d_in, const int* in_sizes, int n_in,
                              void* d_out, int out_size)
{
    const float* x    = (const float*)d_in[0];
    const float* kg   = (const float*)d_in[1];
    const int*   idx  = (const int*)  d_in[2];
    const int*   mask = (const int*)  d_in[3];
    const float* Wkg  = (const float*)d_in[4];
    const float* bkg  = (const float*)d_in[5];
    const float* W1a  = (const float*)d_in[6];
    const float* b1a  = (const float*)d_in[7];
    const float* W1b  = (const float*)d_in[8];
    const float* b1b  = (const float*)d_in[9];
    const float* W1c  = (const float*)d_in[10];
    const float* b1c  = (const float*)d_in[11];
    const float* W1d  = (const float*)d_in[12];
    const float* b1d  = (const float*)d_in[13];
    const float* W2   = (const float*)d_in[14];
    const float* b2   = (const float*)d_in[15];
    float* out = (float*)d_out;

    float *h1, *h2, *h3, *h4, *know, *wt;
    int *cnt, *cidx;
    cudaGetSymbolAddress((void**)&h1,   g_h1);
    cudaGetSymbolAddress((void**)&h2,   g_h2);
    cudaGetSymbolAddress((void**)&h3,   g_h3);
    cudaGetSymbolAddress((void**)&h4,   g_h4);
    cudaGetSymbolAddress((void**)&know, g_know);
    cudaGetSymbolAddress((void**)&wt,   g_wt);
    cudaGetSymbolAddress((void**)&cnt,  g_cnt);
    cudaGetSymbolAddress((void**)&cidx, g_cidx);

    // 1) setup: mask compaction (1024 blocks) + weight tf32 cvt (264 blocks)
    setup_kernel<<<1288, 256>>>(idx, mask, cidx, cnt, W1a, W1b, W1c, W1d, W2);
    // 2) fused: L1a GEMM (256 blocks, CVTA from raw x) || knowledge (2048 blocks)
    fused_l1a_know_kernel<<<L1A_BLOCKS + B_SZ / 4, 256>>>(
        x, wt + W1A_OFF, b1a, h1, kg, Wkg, bkg, cidx, cnt, know);
    // 3) L1b: [8192,128] @ [128,512]  BM=128/BK=16, 3-stage pipeline
    tgemm2_kernel<128, 16, 3, true, false, true><<<dim3(512 / 64, B_SZ / 128), 256>>>(
        h1, wt + W1B_OFF, b1b, nullptr, h2, B_SZ, 512, 128);
    // 4) L1c: [8192,512] @ [512,128]  BM=64/BK=32, 2-stage (proven)
    tgemm2_kernel<64, 32, 2, true, false, true><<<dim3(128 / 64, B_SZ / 64), 256>>>(
        h2, wt + W1C_OFF, b1c, nullptr, h3, B_SZ, 128, 512);
    // 5) L1d: [8192,128] @ [128,64] + knowledge  BM=64/BK=32, 2-stage (proven)
    tgemm2_kernel<64, 32, 2, true, true, true><<<dim3(CC / 64, B_SZ / 64), 256>>>(
        h3, wt + W1D_OFF, b1d, know, h4, B_SZ, CC, 128);
    // 6) L2: [8192,64] @ [64,1024]  BM=128/BK=16, 3-stage (fp32 out)
    tgemm2_kernel<128, 16, 3, false, false, false><<<dim3(OUT_SZ / 64, B_SZ / 128), 256>>>(
        h4, wt + W2_OFF, b2, nullptr, out, B_SZ, OUT_SZ, CC);
}

// round 15
// speedup vs baseline: 1.1221x; 1.0043x over previous
#include <cuda_runtime.h>
#include <cuda_bf16.h>
#include <cstdint>

// Shapes (fixed per reference)
#define B_SZ     8192
#define K_SZ     50
#define KG_DIM   64
#define IN_SZ    512
#define CC       64
#define OUT_SZ   1024

// ---------------------------------------------------------------------------
// Scratch (static device globals -- no runtime allocation allowed)
// ---------------------------------------------------------------------------
__device__ __align__(16) float g_h1[B_SZ * 128];
__device__ __align__(16) float g_h2[B_SZ * 512];
__device__ __align__(16) float g_h3p[2 * B_SZ * 128];   // L1c split-K partials
__device__ __align__(16) float g_h4[B_SZ * CC];
__device__ __align__(16) float g_know[B_SZ * CC];
__device__ __align__(16) float g_wt[270336];   // tf32-rounded weights (packed)
__device__ int   g_cnt[B_SZ];
__device__ int   g_cidx[B_SZ * K_SZ];

// packed weight offsets (floats)
#define W1A_OFF 0
#define W1B_OFF 65536
#define W1C_OFF 131072
#define W1D_OFF 196608
#define W2_OFF  204800

// ---------------------------------------------------------------------------
// tf32 / mma / cp.async helpers
// ---------------------------------------------------------------------------
__device__ __forceinline__ float to_tf32(float x) {
    uint32_t u;
    asm("cvt.rna.tf32.f32 %0, %1;" : "=r"(u) : "f"(x));
    return __uint_as_float(u);
}
__device__ __forceinline__ float4 cvt4(float4 v) {
    return make_float4(to_tf32(v.x), to_tf32(v.y), to_tf32(v.z), to_tf32(v.w));
}
__device__ __forceinline__ void mma_tf32(float* d, const uint32_t* a, const uint32_t* b) {
    asm volatile(
        "mma.sync.aligned.m16n8k8.row.col.f32.tf32.tf32.f32 "
        "{%0,%1,%2,%3}, {%4,%5,%6,%7}, {%8,%9}, {%0,%1,%2,%3};"
        : "+f"(d[0]), "+f"(d[1]), "+f"(d[2]), "+f"(d[3])
        : "r"(a[0]), "r"(a[1]), "r"(a[2]), "r"(a[3]), "r"(b[0]), "r"(b[1]));
}
__device__ __forceinline__ void cp16(void* smem_dst, const void* gsrc) {
    unsigned s = (unsigned)__cvta_generic_to_shared(smem_dst);
    asm volatile("cp.async.ca.shared.global [%0], [%1], 16;" :: "r"(s), "l"(gsrc));
}
__device__ __forceinline__ void cp_commit() { asm volatile("cp.async.commit_group;"); }
template <int N>
__device__ __forceinline__ void cp_wait() {
    asm volatile("cp.async.wait_group %0;" :: "n"(N));
}

// ---------------------------------------------------------------------------
// Setup kernel: blocks 0..1023 = mask compaction (8 rows/block);
//               blocks 1024..1287 = weight tf32 preconvert (256 float4/block).
// ---------------------------------------------------------------------------
__global__ void __launch_bounds__(256) setup_kernel(
    const int* __restrict__ idx, const int* __restrict__ mask,
    int* __restrict__ cidx, int* __restrict__ cnt,
    const float* __restrict__ W1a, const float* __restrict__ W1b,
    const float* __restrict__ W1c, const float* __restrict__ W1d,
    const float* __restrict__ W2)
{
    if (blockIdx.x < 1024) {
        int b = blockIdx.x * 8 + (threadIdx.x >> 5);
        int l = threadIdx.x & 31;
        int base = b * K_SZ;
        int c = 0;
        #pragma unroll
        for (int k0 = 0; k0 < K_SZ; k0 += 32) {
            int k = k0 + l;
            bool m = (k < K_SZ) && (mask[base + k] != 0);
            unsigned bal = __ballot_sync(0xffffffffu, m);
            int pos = c + __popc(bal & ((1u << l) - 1u));
            if (m) cidx[base + pos] = idx[base + k];
            c += __popc(bal);
        }
        if (l == 0) cnt[b] = c;
        return;
    }
    int j = (blockIdx.x - 1024) * 256 + threadIdx.x;   // float4 index, < 67584
    if (j >= 67584) return;
    const float* src; int dst;
    if      (j < 16384) { src = W1a; dst = W1A_OFF / 4; }
    else if (j < 32768) { src = W1b; dst = W1B_OFF / 4; j -= 16384; }
    else if (j < 49152) { src = W1c; dst = W1C_OFF / 4; j -= 32768; }
    else if (j < 51200) { src = W1d; dst = W1D_OFF / 4; j -= 49152; }
    else                { src = W2;  dst = W2_OFF  / 4; j -= 51200; }
    ((float4*)g_wt)[dst + j] = cvt4(((const float4*)src)[j]);
}

// ---------------------------------------------------------------------------
// GEMM body: tf32 tensor-core GEMM  C = act(A @ W + bias) [+ addk]
// Multi-stage cp.async ring (STAGES buffers), canonical always-commit form.
// AMODE=0: A via cp.async (already tf32-valued).
// AMODE=1: A raw fp32, LDG -> cvt.rna -> STS with register prefetch.
// AMODE=2: A = to_tf32(relu(A[i] + A2[i] + biasK[col])) -- fused split-K
//          reduction + bias + relu of the PREVIOUS layer during staging.
// PARTIAL=true: epilogue writes raw fp32 accumulators (no bias/relu/round).
// 256 threads = 8 warps as 4(m) x 2(n); BN=64; frag mapping = Round-8 proven.
// lda = A row stride (may exceed K for split-K column windows).
// ---------------------------------------------------------------------------
template <int BM_, int BK_, int STAGES, bool RELU, bool ADDK, bool ROUND,
          int AMODE, bool PARTIAL>
__device__ __forceinline__ void gemm_body(
    float* smem, int bxn, int bym,
    const float* __restrict__ A, const float* __restrict__ A2,
    const float* __restrict__ biasK,
    const float* __restrict__ W,
    const float* __restrict__ bias, const float* __restrict__ addk,
    float* __restrict__ C, int M, int N, int K, int lda)
{
    constexpr int BN_ = 64;
    constexpr int ALD = BK_ + 4;
    constexpr int BLD = BN_ + 4;
    constexpr int MT  = BM_ / 64;
    constexpr int A_PT = (BM_ * BK_ / 4) / 256;
    constexpr int B_PT = (BK_ * BN_ / 4) / 256;
    constexpr int ACOLS4 = BK_ / 4;
    constexpr int ASZ = BM_ * ALD;
    constexpr int BSZ = BK_ * BLD;

    float* As = smem;                   // [STAGES][ASZ]
    float* Bs = smem + STAGES * ASZ;    // [STAGES][BSZ]

    int tid = threadIdx.x;
    int m0 = bym * BM_;
    int n0 = bxn * BN_;

    // global->smem load mappings
    int a_off[A_PT];
    const float* Ap[A_PT];
    const float* A2p[A_PT];
    const float* Bkp[A_PT];
    #pragma unroll
    for (int t = 0; t < A_PT; t++) {
        int id = tid + t * 256;
        int ar = id / ACOLS4, ac = (id % ACOLS4) * 4;
        a_off[t] = ar * ALD + ac;
        Ap[t] = A + (long)(m0 + ar) * lda + ac;
        if (AMODE == 2) {
            A2p[t] = A2 + (long)(m0 + ar) * lda + ac;
            Bkp[t] = biasK + ac;
        }
    }
    int b_off[B_PT];
    const float* Bp[B_PT];
    #pragma unroll
    for (int t = 0; t < B_PT; t++) {
        int id = tid + t * 256;
        int br = id >> 4, bc = (id & 15) * 4;
        b_off[t] = br * BLD + bc;
        Bp[t] = W + (long)br * N + n0 + bc;
    }

    // warp / fragment coordinates
    int wid = tid >> 5;
    int lane = tid & 31;
    int g  = lane >> 2;
    int tg = lane & 3;
    int wm = wid & 3;
    int wn = wid >> 2;
    int wmb = wm * (BM_ / 4);
    int wnb = wn * 32;

    float acc[MT][4][4];
    #pragma unroll
    for (int mt = 0; mt < MT; mt++)
        #pragma unroll
        for (int nt = 0; nt < 4; nt++)
            #pragma unroll
            for (int r = 0; r < 4; r++) acc[mt][nt][r] = 0.f;

    int nchunks = K / BK_;
    float4 pa[A_PT], pa2[A_PT], bk4[A_PT];   // register prefetch (AMODE!=0)

    // prologue: stages 0..STAGES-2
    #pragma unroll
    for (int s = 0; s < STAGES - 1; s++) {
        if (s < nchunks) {
            if (AMODE != 0) {
                #pragma unroll
                for (int t = 0; t < A_PT; t++) {
                    pa[t] = *(const float4*)Ap[t]; Ap[t] += BK_;
                    if (AMODE == 2) {
                        pa2[t] = *(const float4*)A2p[t]; A2p[t] += BK_;
                        bk4[t] = *(const float4*)Bkp[t]; Bkp[t] += BK_;
                    }
                }
                #pragma unroll
                for (int t = 0; t < A_PT; t++) {
                    float4 v = pa[t];
                    if (AMODE == 2) {
                        v.x = fmaxf(pa[t].x + pa2[t].x + bk4[t].x, 0.f);
                        v.y = fmaxf(pa[t].y + pa2[t].y + bk4[t].y, 0.f);
                        v.z = fmaxf(pa[t].z + pa2[t].z + bk4[t].z, 0.f);
                        v.w = fmaxf(pa[t].w + pa2[t].w + bk4[t].w, 0.f);
                    }
                    *(float4*)&As[s * ASZ + a_off[t]] = cvt4(v);
                }
            } else {
                #pragma unroll
                for (int t = 0; t < A_PT; t++) { cp16(&As[s * ASZ + a_off[t]], Ap[t]); Ap[t] += BK_; }
            }
            #pragma unroll
            for (int t = 0; t < B_PT; t++) { cp16(&Bs[s * BSZ + b_off[t]], Bp[t]); Bp[t] += (long)BK_ * N; }
        }
        cp_commit();
    }
    if (AMODE != 0 && (STAGES - 1 < nchunks)) {
        #pragma unroll
        for (int t = 0; t < A_PT; t++) {
            pa[t] = *(const float4*)Ap[t]; Ap[t] += BK_;
            if (AMODE == 2) {
                pa2[t] = *(const float4*)A2p[t]; A2p[t] += BK_;
                bk4[t] = *(const float4*)Bkp[t]; Bkp[t] += BK_;
            }
        }
    }

    for (int kt = 0; kt < nchunks; kt++) {
        cp_wait<STAGES - 2>();
        __syncthreads();

        int pf = kt + STAGES - 1;
        if (pf < nchunks) {
            int pb = pf % STAGES;
            if (AMODE != 0) {
                #pragma unroll
                for (int t = 0; t < A_PT; t++) {
                    float4 v = pa[t];
                    if (AMODE == 2) {
                        v.x = fmaxf(pa[t].x + pa2[t].x + bk4[t].x, 0.f);
                        v.y = fmaxf(pa[t].y + pa2[t].y + bk4[t].y, 0.f);
                        v.z = fmaxf(pa[t].z + pa2[t].z + bk4[t].z, 0.f);
                        v.w = fmaxf(pa[t].w + pa2[t].w + bk4[t].w, 0.f);
                    }
                    *(float4*)&As[pb * ASZ + a_off[t]] = cvt4(v);
                }
            } else {
                #pragma unroll
                for (int t = 0; t < A_PT; t++) { cp16(&As[pb * ASZ + a_off[t]], Ap[t]); Ap[t] += BK_; }
            }
            #pragma unroll
            for (int t = 0; t < B_PT; t++) { cp16(&Bs[pb * BSZ + b_off[t]], Bp[t]); Bp[t] += (long)BK_ * N; }
        }
        cp_commit();   // always commit (empty groups at tail keep the count advancing)

        if (AMODE != 0 && (pf + 1 < nchunks)) {   // prefetch next A chunk; overlaps compute
            #pragma unroll
            for (int t = 0; t < A_PT; t++) {
                pa[t] = *(const float4*)Ap[t]; Ap[t] += BK_;
                if (AMODE == 2) {
                    pa2[t] = *(const float4*)A2p[t]; A2p[t] += BK_;
                    bk4[t] = *(const float4*)Bkp[t]; Bkp[t] += BK_;
                }
            }
        }

        const float* Asc = As + (kt % STAGES) * ASZ;
        const float* Bsc = Bs + (kt % STAGES) * BSZ;
        #pragma unroll
        for (int ks = 0; ks < BK_; ks += 8) {
            uint32_t af[MT][4];
            #pragma unroll
            for (int mt = 0; mt < MT; mt++) {
                const float* ap = &Asc[(wmb + mt * 16 + g) * ALD + ks + tg];
                af[mt][0] = __float_as_uint(ap[0]);
                af[mt][1] = __float_as_uint(ap[8 * ALD]);
                af[mt][2] = __float_as_uint(ap[4]);
                af[mt][3] = __float_as_uint(ap[8 * ALD + 4]);
            }
            uint32_t bf[4][2];
            #pragma unroll
            for (int nt = 0; nt < 4; nt++) {
                const float* bp = &Bsc[(ks + tg) * BLD + wnb + nt * 8 + g];
                bf[nt][0] = __float_as_uint(bp[0]);
                bf[nt][1] = __float_as_uint(bp[4 * BLD]);
            }
            #pragma unroll
            for (int mt = 0; mt < MT; mt++)
                #pragma unroll
                for (int nt = 0; nt < 4; nt++)
                    mma_tf32(acc[mt][nt], af[mt], bf[nt]);
        }
    }

    // epilogue (exact fp32; PARTIAL stores raw accumulators)
    #pragma unroll
    for (int nt = 0; nt < 4; nt++) {
        int col = n0 + wnb + nt * 8 + tg * 2;
        float2 bs2;
        if (PARTIAL) bs2 = make_float2(0.f, 0.f);
        else         bs2 = *(const float2*)&bias[col];
        #pragma unroll
        for (int mt = 0; mt < MT; mt++) {
            int r0 = m0 + wmb + mt * 16 + g;
            int r1 = r0 + 8;
            float v00 = acc[mt][nt][0] + bs2.x;
            float v01 = acc[mt][nt][1] + bs2.y;
            float v10 = acc[mt][nt][2] + bs2.x;
            float v11 = acc[mt][nt][3] + bs2.y;
            if (RELU) {
                v00 = fmaxf(v00, 0.f); v01 = fmaxf(v01, 0.f);
                v10 = fmaxf(v10, 0.f); v11 = fmaxf(v11, 0.f);
            }
            if (ADDK) {
                float2 k0 = *(const float2*)&addk[(long)r0 * N + col];
                float2 k1 = *(const float2*)&addk[(long)r1 * N + col];
                v00 += k0.x; v01 += k0.y; v10 += k1.x; v11 += k1.y;
            }
            if (ROUND) {
                v00 = to_tf32(v00); v01 = to_tf32(v01);
                v10 = to_tf32(v10); v11 = to_tf32(v11);
            }
            *(float2*)&C[(long)r0 * N + col] = make_float2(v00, v01);
            *(float2*)&C[(long)r1 * N + col] = make_float2(v10, v11);
        }
    }
}

// ---------------------------------------------------------------------------
// Knowledge body (unchanged from the passing Round-13 version).
// ---------------------------------------------------------------------------
__device__ __forceinline__ void knowledge_body(
    float* smem, int kb,
    const float* __restrict__ kg, const float* __restrict__ Wkg,
    const float* __restrict__ bkg, const int* __restrict__ cidx,
    const int* __restrict__ cnt, float* __restrict__ know)
{
    float* Ws = smem;                // [64*68] tf32 Wkg [k][n]
    float* Ag = smem + KG_DIM * 68;  // [4][16*68]

    int tid = threadIdx.x;
    for (int i = tid * 4; i < KG_DIM * CC; i += 256 * 4) {
        int k = i >> 6, c = i & 63;
        *(float4*)&Ws[k * 68 + c] = cvt4(*(const float4*)&Wkg[i]);
    }
    __syncthreads();

    int w = tid >> 5, l = tid & 31;
    int pair = w >> 1, h = w & 1;
    int g = l >> 2, tg = l & 3;
    int b = kb * 4 + pair;
    float* Agp = Ag + pair * 16 * 68;
    int barid = 1 + pair;

    float bf[4][2];
    #pragma unroll
    for (int n8 = 0; n8 < 4; n8++) {
        float2 t = *(const float2*)&bkg[h * 32 + n8 * 8 + 2 * tg];
        bf[n8][0] = t.x; bf[n8][1] = t.y;
    }

    int n = cnt[b];
    const int* cp = cidx + b * K_SZ;

    float cs[4][2];
    #pragma unroll
    for (int n8 = 0; n8 < 4; n8++) { cs[n8][0] = 0.f; cs[n8][1] = 0.f; }

    // prefetch chunk 0 rows (this warp gathers rows r%2==h)
    float2 pr[8];
    {
        int nr0 = min(16, n);
        #pragma unroll
        for (int i = 0; i < 8; i++) {
            int r = 2 * i + h;
            if (r < nr0) pr[i] = *(const float2*)(kg + (long)cp[r] * KG_DIM + 2 * l);
        }
    }

    for (int c0 = 0; c0 < n; c0 += 16) {
        int nr = min(16, n - c0);
        #pragma unroll
        for (int i = 0; i < 8; i++) {
            int r = 2 * i + h;
            if (r < nr)
                *(float2*)&Agp[r * 68 + 2 * l] =
                    make_float2(to_tf32(pr[i].x), to_tf32(pr[i].y));
        }
        asm volatile("bar.sync %0, 64;" :: "r"(barid) : "memory");

        int c1 = c0 + 16;
        if (c1 < n) {
            int nrn = min(16, n - c1);
            #pragma unroll
            for (int i = 0; i < 8; i++) {
                int r = 2 * i + h;
                if (r < nrn) pr[i] = *(const float2*)(kg + (long)cp[c1 + r] * KG_DIM + 2 * l);
            }
        }

        float acc[4][4];
        #pragma unroll
        for (int n8 = 0; n8 < 4; n8++)
            #pragma unroll
            for (int r = 0; r < 4; r++) acc[n8][r] = 0.f;

        #pragma unroll
        for (int ks = 0; ks < KG_DIM; ks += 8) {
            uint32_t af[4];
            const float* ap = &Agp[g * 68 + ks + tg];
            af[0] = __float_as_uint(ap[0]);
            af[1] = __float_as_uint(ap[8 * 68]);
            af[2] = __float_as_uint(ap[4]);
            af[3] = __float_as_uint(ap[8 * 68 + 4]);
            #pragma unroll
            for (int n8 = 0; n8 < 4; n8++) {
                uint32_t bfr[2];
                const float* bp = &Ws[(ks + tg) * 68 + h * 32 + n8 * 8 + g];
                bfr[0] = __float_as_uint(bp[0]);
                bfr[1] = __float_as_uint(bp[4 * 68]);
                mma_tf32(acc[n8], af, bfr);
            }
        }

        bool v0 = (g < nr);
        bool v1 = (g + 8 < nr);
        #pragma unroll
        for (int n8 = 0; n8 < 4; n8++) {
            if (v0) {
                cs[n8][0] += fmaxf(acc[n8][0] + bf[n8][0], 0.f);
                cs[n8][1] += fmaxf(acc[n8][1] + bf[n8][1], 0.f);
            }
            if (v1) {
                cs[n8][0] += fmaxf(acc[n8][2] + bf[n8][0], 0.f);
                cs[n8][1] += fmaxf(acc[n8][3] + bf[n8][1], 0.f);
            }
        }
        asm volatile("bar.sync %0, 64;" :: "r"(barid) : "memory");
    }

    #pragma unroll
    for (int n8 = 0; n8 < 4; n8++)
        #pragma unroll
        for (int j = 0; j < 2; j++) {
            float v = cs[n8][j];
            v += __shfl_xor_sync(0xffffffffu, v, 4);
            v += __shfl_xor_sync(0xffffffffu, v, 8);
            v += __shfl_xor_sync(0xffffffffu, v, 16);
            cs[n8][j] = v;
        }

    if (g < 4) {
        float o0 = 0.f, o1 = 0.f;
        #pragma unroll
        for (int n8 = 0; n8 < 4; n8++)
            if (n8 == g) { o0 = cs[n8][0]; o1 = cs[n8][1]; }
        // NOTE: h*32 offset is load-bearing (Round-10 regression)
        *(float2*)&know[(long)b * CC + h * 32 + g * 8 + 2 * tg] = make_float2(o0, o1);
    }
}

// ---------------------------------------------------------------------------
// Fused kernel: L1a GEMM blocks (0..255, 2-stage, CVTA from raw x) +
//               knowledge blocks (256..2303).
// Union static smem: max(gemm 8960, knowledge 8704) floats = 35.8 KB.
// ---------------------------------------------------------------------------
#define L1A_BLOCKS 256
__global__ void __launch_bounds__(256) fused_l1a_know_kernel(
    const float* __restrict__ x, const float* __restrict__ w1a,
    const float* __restrict__ b1a, float* __restrict__ h1,
    const float* __restrict__ kg, const float* __restrict__ Wkg,
    const float* __restrict__ bkg, const int* __restrict__ cidx,
    const int* __restrict__ cnt, float* __restrict__ know)
{
    __shared__ __align__(16) float smem[8960];
    if (blockIdx.x < L1A_BLOCKS) {
        gemm_body<64, 32, 2, true, false, true, 1, false>(
            smem, blockIdx.x & 1, blockIdx.x >> 1,
            x, nullptr, nullptr, w1a, b1a, nullptr, h1, B_SZ, 128, IN_SZ, IN_SZ);
    } else {
        knowledge_body(smem, blockIdx.x - L1A_BLOCKS, kg, Wkg, bkg, cidx, cnt, know);
    }
}

// ---------------------------------------------------------------------------
// Standalone GEMM kernel wrappers
// ---------------------------------------------------------------------------
template <int BM_, int BK_, int STAGES, bool RELU, bool ADDK, bool ROUND>
__global__ void __launch_bounds__(256) tgemm2_kernel(
    const float* __restrict__ A, const float* __restrict__ W,
    const float* __restrict__ bias, const float* __restrict__ addk,
    float* __restrict__ C, int M, int N, int K)
{
    constexpr int SM_FLOATS = STAGES * BM_ * (BK_ + 4) + STAGES * BK_ * 68;
    __shared__ __align__(16) float smem[SM_FLOATS];
    gemm_body<BM_, BK_, STAGES, RELU, ADDK, ROUND, 0, false>(
        smem, blockIdx.x, blockIdx.y, A, nullptr, nullptr, W, bias, addk,
        C, M, N, K, K);
}

// Split-K partial GEMM: blockIdx.z selects K-half; raw fp32 partial output.
__global__ void __launch_bounds__(256) tgemm_part_kernel(
    const float* __restrict__ A, const float* __restrict__ W,
    float* __restrict__ C, int M, int N, int KH, int lda)
{
    constexpr int SM_FLOATS = 2 * 64 * 36 + 2 * 32 * 68;
    __shared__ __align__(16) float smem[SM_FLOATS];
    int z = blockIdx.z;
    gemm_body<64, 32, 2, false, false, false, 0, true>(
        smem, blockIdx.x, blockIdx.y,
        A + (long)z * KH, nullptr, nullptr,
        W + (long)z * KH * N, nullptr, nullptr,
        C + (long)z * M * N, M, N, KH, lda);
}

// Fused split-K reduce + bias + relu (previous layer) in A-staging.
__global__ void __launch_bounds__(256) tgemm_suma_kernel(
    const float* __restrict__ P0, const float* __restrict__ P1,
    const float* __restrict__ biasK, const float* __restrict__ W,
    const float* __restrict__ bias, const float* __restrict__ addk,
    float* __restrict__ C, int M, int N, int K)
{
    constexpr int SM_FLOATS = 2 * 64 * 36 + 2 * 32 * 68;
    __shared__ __align__(16) float smem[SM_FLOATS];
    gemm_body<64, 32, 2, true, true, true, 2, false>(
        smem, blockIdx.x, blockIdx.y, P0, P1, biasK, W, bias, addk,
        C, M, N, K, K);
}

// ---------------------------------------------------------------------------
// Launcher
// Input order (metadata): x, kg, idx, mask, Wkg, bkg, W1a,b1a, W1b,b1b,
//                         W1c,b1c, W1d,b1d, W2,b2.  Output: float [8192,1024].
// ---------------------------------------------------------------------------
extern "C" void kernel_launch(void* const* d_in, const int* in_sizes, int n_in,
                              void* d_out, int out_size)
{
    const float* x    = (const float*)d_in[0];
    const float* kg   = (const float*)d_in[1];
    const int*   idx  = (const int*)  d_in[2];
    const int*   mask = (const int*)  d_in[3];
    const float* Wkg  = (const float*)d_in[4];
    const float* bkg  = (const float*)d_in[5];
    const float* W1a  = (const float*)d_in[6];
    const float* b1a  = (const float*)d_in[7];
    const float* W1b  = (const float*)d_in[8];
    const float* b1b  = (const float*)d_in[9];
    const float* W1c  = (const float*)d_in[10];
    const float* b1c  = (const float*)d_in[11];
    const float* W1d  = (const float*)d_in[12];
    const float* b1d  = (const float*)d_in[13];
    const float* W2   = (const float*)d_in[14];
    const float* b2   = (const float*)d_in[15];
    float* out = (float*)d_out;

    float *h1, *h2, *h3p, *h4, *know, *wt;
    int *cnt, *cidx;
    cudaGetSymbolAddress((void**)&h1,   g_h1);
    cudaGetSymbolAddress((void**)&h2,   g_h2);
    cudaGetSymbolAddress((void**)&h3p,  g_h3p);
    cudaGetSymbolAddress((void**)&h4,   g_h4);
    cudaGetSymbolAddress((void**)&know, g_know);
    cudaGetSymbolAddress((void**)&wt,   g_wt);
    cudaGetSymbolAddress((void**)&cnt,  g_cnt);
    cudaGetSymbolAddress((void**)&cidx, g_cidx);

    // 1) setup: mask compaction (1024 blocks) + weight tf32 cvt (264 blocks)
    setup_kernel<<<1288, 256>>>(idx, mask, cidx, cnt, W1a, W1b, W1c, W1d, W2);
    // 2) fused: L1a GEMM (256 blocks, CVTA from raw x) || knowledge (2048 blocks)
    fused_l1a_know_kernel<<<L1A_BLOCKS + B_SZ / 4, 256>>>(
        x, wt + W1A_OFF, b1a, h1, kg, Wkg, bkg, cidx, cnt, know);
    // 3) L1b: [8192,128] @ [128,512]  BM=128/BK=16, 3-stage pipeline
    tgemm2_kernel<128, 16, 3, true, false, true><<<dim3(512 / 64, B_SZ / 128), 256>>>(
        h1, wt + W1B_OFF, b1b, nullptr, h2, B_SZ, 512, 128);
    // 4) L1c split-K: [8192,512] @ [512,128] -> two K=256 partials, 512 blocks
    tgemm_part_kernel<<<dim3(128 / 64, B_SZ / 64, 2), 256>>>(
        h2, wt + W1C_OFF, h3p, B_SZ, 128, 256, 512);
    // 5) L1d: A = relu(p0+p1+b1c) fused in staging; [8192,128]@[128,64] + know
    tgemm_suma_kernel<<<dim3(CC / 64, B_SZ / 64), 256>>>(
        h3p, h3p + (long)B_SZ * 128, b1c, wt + W1D_OFF, b1d, know,
        h4, B_SZ, CC, 128);
    // 6) L2: [8192,64] @ [64,1024]  BM=128/BK=16, 3-stage (fp32 out)
    tgemm2_kernel<128, 16, 3, false, false, false><<<dim3(OUT_SZ / 64, B_SZ / 128), 256>>>(
        h4, wt + W2_OFF, b2, nullptr, out, B_SZ, OUT_SZ, CC);
}

// round 17
// speedup vs baseline: 1.2773x; 1.1383x over previous
#include <cuda_runtime.h>
#include <cuda_bf16.h>
#include <cstdint>

// Shapes (fixed per reference)
#define B_SZ     8192
#define K_SZ     50
#define KG_DIM   64
#define IN_SZ    512
#define CC       64
#define OUT_SZ   1024

// ---------------------------------------------------------------------------
// Scratch (static device globals -- no runtime allocation allowed)
// ---------------------------------------------------------------------------
__device__ __align__(16) float g_h1[B_SZ * 128];
__device__ __align__(16) float g_h2[B_SZ * 512];
__device__ __align__(16) float g_h3p[2 * B_SZ * 128];   // L1c split-K partials
__device__ __align__(16) float g_h4[B_SZ * CC];
__device__ __align__(16) float g_know[B_SZ * CC];
__device__ __align__(16) float g_wt[270336];   // tf32-rounded weights (packed)
__device__ int   g_cnt[B_SZ];
__device__ int   g_cidx[B_SZ * K_SZ];

// packed weight offsets (floats)
#define W1A_OFF 0
#define W1B_OFF 65536
#define W1C_OFF 131072
#define W1D_OFF 196608
#define W2_OFF  204800

// ---------------------------------------------------------------------------
// tf32 / mma / cp.async helpers
// ---------------------------------------------------------------------------
__device__ __forceinline__ float to_tf32(float x) {
    uint32_t u;
    asm("cvt.rna.tf32.f32 %0, %1;" : "=r"(u) : "f"(x));
    return __uint_as_float(u);
}
__device__ __forceinline__ float4 cvt4(float4 v) {
    return make_float4(to_tf32(v.x), to_tf32(v.y), to_tf32(v.z), to_tf32(v.w));
}
__device__ __forceinline__ void mma_tf32(float* d, const uint32_t* a, const uint32_t* b) {
    asm volatile(
        "mma.sync.aligned.m16n8k8.row.col.f32.tf32.tf32.f32 "
        "{%0,%1,%2,%3}, {%4,%5,%6,%7}, {%8,%9}, {%0,%1,%2,%3};"
        : "+f"(d[0]), "+f"(d[1]), "+f"(d[2]), "+f"(d[3])
        : "r"(a[0]), "r"(a[1]), "r"(a[2]), "r"(a[3]), "r"(b[0]), "r"(b[1]));
}
__device__ __forceinline__ void cp16(void* smem_dst, const void* gsrc) {
    unsigned s = (unsigned)__cvta_generic_to_shared(smem_dst);
    asm volatile("cp.async.ca.shared.global [%0], [%1], 16;" :: "r"(s), "l"(gsrc));
}
__device__ __forceinline__ void cp_commit() { asm volatile("cp.async.commit_group;"); }
template <int N>
__device__ __forceinline__ void cp_wait() {
    asm volatile("cp.async.wait_group %0;" :: "n"(N));
}

// ---------------------------------------------------------------------------
// Setup kernel: blocks 0..1023 = mask compaction (8 rows/block);
//               blocks 1024..1287 = weight tf32 preconvert (256 float4/block).
// ---------------------------------------------------------------------------
__global__ void __launch_bounds__(256) setup_kernel(
    const int* __restrict__ idx, const int* __restrict__ mask,
    int* __restrict__ cidx, int* __restrict__ cnt,
    const float* __restrict__ W1a, const float* __restrict__ W1b,
    const float* __restrict__ W1c, const float* __restrict__ W1d,
    const float* __restrict__ W2)
{
    if (blockIdx.x < 1024) {
        int b = blockIdx.x * 8 + (threadIdx.x >> 5);
        int l = threadIdx.x & 31;
        int base = b * K_SZ;
        int c = 0;
        #pragma unroll
        for (int k0 = 0; k0 < K_SZ; k0 += 32) {
            int k = k0 + l;
            bool m = (k < K_SZ) && (mask[base + k] != 0);
            unsigned bal = __ballot_sync(0xffffffffu, m);
            int pos = c + __popc(bal & ((1u << l) - 1u));
            if (m) cidx[base + pos] = idx[base + k];
            c += __popc(bal);
        }
        if (l == 0) cnt[b] = c;
        return;
    }
    int j = (blockIdx.x - 1024) * 256 + threadIdx.x;   // float4 index, < 67584
    if (j >= 67584) return;
    const float* src; int dst;
    if      (j < 16384) { src = W1a; dst = W1A_OFF / 4; }
    else if (j < 32768) { src = W1b; dst = W1B_OFF / 4; j -= 16384; }
    else if (j < 49152) { src = W1c; dst = W1C_OFF / 4; j -= 32768; }
    else if (j < 51200) { src = W1d; dst = W1D_OFF / 4; j -= 49152; }
    else                { src = W2;  dst = W2_OFF  / 4; j -= 51200; }
    ((float4*)g_wt)[dst + j] = cvt4(((const float4*)src)[j]);
}

// ---------------------------------------------------------------------------
// GEMM body: tf32 tensor-core GEMM  C = act(A @ W + bias) [+ addk]
// Multi-stage cp.async ring (STAGES buffers), canonical always-commit form.
// BLD = BN + 8 (=72): B-frag bank index = (8*tg + g) mod 32 -- conflict-free.
// (BLD = BN+4 = 68 gives (4*tg+g): 2-way conflicted -- the Round-14 L1 ceiling.)
// AMODE=0: A via cp.async (already tf32-valued).
// AMODE=1: A raw fp32, LDG -> cvt.rna -> STS with register prefetch.
// AMODE=2: A = to_tf32(relu(A[i] + A2[i] + biasK[col])) -- fused split-K
//          reduction + bias + relu of the PREVIOUS layer during staging.
// PARTIAL=true: epilogue writes raw fp32 accumulators (no bias/relu/round).
// 256 threads = 8 warps as 4(m) x 2(n); BN=64.
// ---------------------------------------------------------------------------
template <int BM_, int BK_, int STAGES, bool RELU, bool ADDK, bool ROUND,
          int AMODE, bool PARTIAL>
__device__ __forceinline__ void gemm_body(
    float* smem, int bxn, int bym,
    const float* __restrict__ A, const float* __restrict__ A2,
    const float* __restrict__ biasK,
    const float* __restrict__ W,
    const float* __restrict__ bias, const float* __restrict__ addk,
    float* __restrict__ C, int M, int N, int K, int lda)
{
    constexpr int BN_ = 64;
    constexpr int ALD = BK_ + 4;     // A-frag bank = (4g+tg): conflict-free
    constexpr int BLD = BN_ + 8;     // 72: B-frag bank = (8tg+g): conflict-free
    constexpr int MT  = BM_ / 64;
    constexpr int A_PT = (BM_ * BK_ / 4) / 256;
    constexpr int B_PT = (BK_ * BN_ / 4) / 256;
    constexpr int ACOLS4 = BK_ / 4;
    constexpr int ASZ = BM_ * ALD;
    constexpr int BSZ = BK_ * BLD;

    float* As = smem;                   // [STAGES][ASZ]
    float* Bs = smem + STAGES * ASZ;    // [STAGES][BSZ]

    int tid = threadIdx.x;
    int m0 = bym * BM_;
    int n0 = bxn * BN_;

    // global->smem load mappings
    int a_off[A_PT];
    const float* Ap[A_PT];
    const float* A2p[A_PT];
    const float* Bkp[A_PT];
    #pragma unroll
    for (int t = 0; t < A_PT; t++) {
        int id = tid + t * 256;
        int ar = id / ACOLS4, ac = (id % ACOLS4) * 4;
        a_off[t] = ar * ALD + ac;
        Ap[t] = A + (long)(m0 + ar) * lda + ac;
        if (AMODE == 2) {
            A2p[t] = A2 + (long)(m0 + ar) * lda + ac;
            Bkp[t] = biasK + ac;
        }
    }
    int b_off[B_PT];
    const float* Bp[B_PT];
    #pragma unroll
    for (int t = 0; t < B_PT; t++) {
        int id = tid + t * 256;
        int br = id >> 4, bc = (id & 15) * 4;
        b_off[t] = br * BLD + bc;
        Bp[t] = W + (long)br * N + n0 + bc;
    }

    // warp / fragment coordinates
    int wid = tid >> 5;
    int lane = tid & 31;
    int g  = lane >> 2;
    int tg = lane & 3;
    int wm = wid & 3;
    int wn = wid >> 2;
    int wmb = wm * (BM_ / 4);
    int wnb = wn * 32;

    float acc[MT][4][4];
    #pragma unroll
    for (int mt = 0; mt < MT; mt++)
        #pragma unroll
        for (int nt = 0; nt < 4; nt++)
            #pragma unroll
            for (int r = 0; r < 4; r++) acc[mt][nt][r] = 0.f;

    int nchunks = K / BK_;
    float4 pa[A_PT], pa2[A_PT], bk4[A_PT];   // register prefetch (AMODE!=0)

    // prologue: stages 0..STAGES-2
    #pragma unroll
    for (int s = 0; s < STAGES - 1; s++) {
        if (s < nchunks) {
            if (AMODE != 0) {
                #pragma unroll
                for (int t = 0; t < A_PT; t++) {
                    pa[t] = *(const float4*)Ap[t]; Ap[t] += BK_;
                    if (AMODE == 2) {
                        pa2[t] = *(const float4*)A2p[t]; A2p[t] += BK_;
                        bk4[t] = *(const float4*)Bkp[t]; Bkp[t] += BK_;
                    }
                }
                #pragma unroll
                for (int t = 0; t < A_PT; t++) {
                    float4 v = pa[t];
                    if (AMODE == 2) {
                        v.x = fmaxf(pa[t].x + pa2[t].x + bk4[t].x, 0.f);
                        v.y = fmaxf(pa[t].y + pa2[t].y + bk4[t].y, 0.f);
                        v.z = fmaxf(pa[t].z + pa2[t].z + bk4[t].z, 0.f);
                        v.w = fmaxf(pa[t].w + pa2[t].w + bk4[t].w, 0.f);
                    }
                    *(float4*)&As[s * ASZ + a_off[t]] = cvt4(v);
                }
            } else {
                #pragma unroll
                for (int t = 0; t < A_PT; t++) { cp16(&As[s * ASZ + a_off[t]], Ap[t]); Ap[t] += BK_; }
            }
            #pragma unroll
            for (int t = 0; t < B_PT; t++) { cp16(&Bs[s * BSZ + b_off[t]], Bp[t]); Bp[t] += (long)BK_ * N; }
        }
        cp_commit();
    }
    if (AMODE != 0 && (STAGES - 1 < nchunks)) {
        #pragma unroll
        for (int t = 0; t < A_PT; t++) {
            pa[t] = *(const float4*)Ap[t]; Ap[t] += BK_;
            if (AMODE == 2) {
                pa2[t] = *(const float4*)A2p[t]; A2p[t] += BK_;
                bk4[t] = *(const float4*)Bkp[t]; Bkp[t] += BK_;
            }
        }
    }

    for (int kt = 0; kt < nchunks; kt++) {
        cp_wait<STAGES - 2>();
        __syncthreads();

        int pf = kt + STAGES - 1;
        if (pf < nchunks) {
            int pb = pf % STAGES;
            if (AMODE != 0) {
                #pragma unroll
                for (int t = 0; t < A_PT; t++) {
                    float4 v = pa[t];
                    if (AMODE == 2) {
                        v.x = fmaxf(pa[t].x + pa2[t].x + bk4[t].x, 0.f);
                        v.y = fmaxf(pa[t].y + pa2[t].y + bk4[t].y, 0.f);
                        v.z = fmaxf(pa[t].z + pa2[t].z + bk4[t].z, 0.f);
                        v.w = fmaxf(pa[t].w + pa2[t].w + bk4[t].w, 0.f);
                    }
                    *(float4*)&As[pb * ASZ + a_off[t]] = cvt4(v);
                }
            } else {
                #pragma unroll
                for (int t = 0; t < A_PT; t++) { cp16(&As[pb * ASZ + a_off[t]], Ap[t]); Ap[t] += BK_; }
            }
            #pragma unroll
            for (int t = 0; t < B_PT; t++) { cp16(&Bs[pb * BSZ + b_off[t]], Bp[t]); Bp[t] += (long)BK_ * N; }
        }
        cp_commit();   // always commit (empty groups at tail keep the count advancing)

        if (AMODE != 0 && (pf + 1 < nchunks)) {   // prefetch next A chunk; overlaps compute
            #pragma unroll
            for (int t = 0; t < A_PT; t++) {
                pa[t] = *(const float4*)Ap[t]; Ap[t] += BK_;
                if (AMODE == 2) {
                    pa2[t] = *(const float4*)A2p[t]; A2p[t] += BK_;
                    bk4[t] = *(const float4*)Bkp[t]; Bkp[t] += BK_;
                }
            }
        }

        const float* Asc = As + (kt % STAGES) * ASZ;
        const float* Bsc = Bs + (kt % STAGES) * BSZ;
        #pragma unroll
        for (int ks = 0; ks < BK_; ks += 8) {
            uint32_t af[MT][4];
            #pragma unroll
            for (int mt = 0; mt < MT; mt++) {
                const float* ap = &Asc[(wmb + mt * 16 + g) * ALD + ks + tg];
                af[mt][0] = __float_as_uint(ap[0]);
                af[mt][1] = __float_as_uint(ap[8 * ALD]);
                af[mt][2] = __float_as_uint(ap[4]);
                af[mt][3] = __float_as_uint(ap[8 * ALD + 4]);
            }
            uint32_t bf[4][2];
            #pragma unroll
            for (int nt = 0; nt < 4; nt++) {
                const float* bp = &Bsc[(ks + tg) * BLD + wnb + nt * 8 + g];
                bf[nt][0] = __float_as_uint(bp[0]);
                bf[nt][1] = __float_as_uint(bp[4 * BLD]);
            }
            #pragma unroll
            for (int mt = 0; mt < MT; mt++)
                #pragma unroll
                for (int nt = 0; nt < 4; nt++)
                    mma_tf32(acc[mt][nt], af[mt], bf[nt]);
        }
    }

    // epilogue (exact fp32; PARTIAL stores raw accumulators)
    #pragma unroll
    for (int nt = 0; nt < 4; nt++) {
        int col = n0 + wnb + nt * 8 + tg * 2;
        float2 bs2;
        if (PARTIAL) bs2 = make_float2(0.f, 0.f);
        else         bs2 = *(const float2*)&bias[col];
        #pragma unroll
        for (int mt = 0; mt < MT; mt++) {
            int r0 = m0 + wmb + mt * 16 + g;
            int r1 = r0 + 8;
            float v00 = acc[mt][nt][0] + bs2.x;
            float v01 = acc[mt][nt][1] + bs2.y;
            float v10 = acc[mt][nt][2] + bs2.x;
            float v11 = acc[mt][nt][3] + bs2.y;
            if (RELU) {
                v00 = fmaxf(v00, 0.f); v01 = fmaxf(v01, 0.f);
                v10 = fmaxf(v10, 0.f); v11 = fmaxf(v11, 0.f);
            }
            if (ADDK) {
                float2 k0 = *(const float2*)&addk[(long)r0 * N + col];
                float2 k1 = *(const float2*)&addk[(long)r1 * N + col];
                v00 += k0.x; v01 += k0.y; v10 += k1.x; v11 += k1.y;
            }
            if (ROUND) {
                v00 = to_tf32(v00); v01 = to_tf32(v01);
                v10 = to_tf32(v10); v11 = to_tf32(v11);
            }
            *(float2*)&C[(long)r0 * N + col] = make_float2(v00, v01);
            *(float2*)&C[(long)r1 * N + col] = make_float2(v10, v11);
        }
    }
}

// ---------------------------------------------------------------------------
// Knowledge body: Ws stride padded 68 -> 72 (same B-frag conflict fix);
// Ag stride stays 68 (A-type pattern (4g+tg): already conflict-free).
// Store offset h*32 is load-bearing (Round-10 regression).
// ---------------------------------------------------------------------------
#define WLD 72
#define AGLD 68
__device__ __forceinline__ void knowledge_body(
    float* smem, int kb,
    const float* __restrict__ kg, const float* __restrict__ Wkg,
    const float* __restrict__ bkg, const int* __restrict__ cidx,
    const int* __restrict__ cnt, float* __restrict__ know)
{
    float* Ws = smem;                   // [64*WLD] tf32 Wkg [k][n]
    float* Ag = smem + KG_DIM * WLD;    // [4][16*AGLD]

    int tid = threadIdx.x;
    for (int i = tid * 4; i < KG_DIM * CC; i += 256 * 4) {
        int k = i >> 6, c = i & 63;
        *(float4*)&Ws[k * WLD + c] = cvt4(*(const float4*)&Wkg[i]);
    }
    __syncthreads();

    int w = tid >> 5, l = tid & 31;
    int pair = w >> 1, h = w & 1;
    int g = l >> 2, tg = l & 3;
    int b = kb * 4 + pair;
    float* Agp = Ag + pair * 16 * AGLD;
    int barid = 1 + pair;

    float bf[4][2];
    #pragma unroll
    for (int n8 = 0; n8 < 4; n8++) {
        float2 t = *(const float2*)&bkg[h * 32 + n8 * 8 + 2 * tg];
        bf[n8][0] = t.x; bf[n8][1] = t.y;
    }

    int n = cnt[b];
    const int* cp = cidx + b * K_SZ;

    float cs[4][2];
    #pragma unroll
    for (int n8 = 0; n8 < 4; n8++) { cs[n8][0] = 0.f; cs[n8][1] = 0.f; }

    // prefetch chunk 0 rows (this warp gathers rows r%2==h)
    float2 pr[8];
    {
        int nr0 = min(16, n);
        #pragma unroll
        for (int i = 0; i < 8; i++) {
            int r = 2 * i + h;
            if (r < nr0) pr[i] = *(const float2*)(kg + (long)cp[r] * KG_DIM + 2 * l);
        }
    }

    for (int c0 = 0; c0 < n; c0 += 16) {
        int nr = min(16, n - c0);
        #pragma unroll
        for (int i = 0; i < 8; i++) {
            int r = 2 * i + h;
            if (r < nr)
                *(float2*)&Agp[r * AGLD + 2 * l] =
                    make_float2(to_tf32(pr[i].x), to_tf32(pr[i].y));
        }
        asm volatile("bar.sync %0, 64;" :: "r"(barid) : "memory");

        int c1 = c0 + 16;
        if (c1 < n) {
            int nrn = min(16, n - c1);
            #pragma unroll
            for (int i = 0; i < 8; i++) {
                int r = 2 * i + h;
                if (r < nrn) pr[i] = *(const float2*)(kg + (long)cp[c1 + r] * KG_DIM + 2 * l);
            }
        }

        float acc[4][4];
        #pragma unroll
        for (int n8 = 0; n8 < 4; n8++)
            #pragma unroll
            for (int r = 0; r < 4; r++) acc[n8][r] = 0.f;

        #pragma unroll
        for (int ks = 0; ks < KG_DIM; ks += 8) {
            uint32_t af[4];
            const float* ap = &Agp[g * AGLD + ks + tg];
            af[0] = __float_as_uint(ap[0]);
            af[1] = __float_as_uint(ap[8 * AGLD]);
            af[2] = __float_as_uint(ap[4]);
            af[3] = __float_as_uint(ap[8 * AGLD + 4]);
            #pragma unroll
            for (int n8 = 0; n8 < 4; n8++) {
                uint32_t bfr[2];
                const float* bp = &Ws[(ks + tg) * WLD + h * 32 + n8 * 8 + g];
                bfr[0] = __float_as_uint(bp[0]);
                bfr[1] = __float_as_uint(bp[4 * WLD]);
                mma_tf32(acc[n8], af, bfr);
            }
        }

        bool v0 = (g < nr);
        bool v1 = (g + 8 < nr);
        #pragma unroll
        for (int n8 = 0; n8 < 4; n8++) {
            if (v0) {
                cs[n8][0] += fmaxf(acc[n8][0] + bf[n8][0], 0.f);
                cs[n8][1] += fmaxf(acc[n8][1] + bf[n8][1], 0.f);
            }
            if (v1) {
                cs[n8][0] += fmaxf(acc[n8][2] + bf[n8][0], 0.f);
                cs[n8][1] += fmaxf(acc[n8][3] + bf[n8][1], 0.f);
            }
        }
        asm volatile("bar.sync %0, 64;" :: "r"(barid) : "memory");
    }

    #pragma unroll
    for (int n8 = 0; n8 < 4; n8++)
        #pragma unroll
        for (int j = 0; j < 2; j++) {
            float v = cs[n8][j];
            v += __shfl_xor_sync(0xffffffffu, v, 4);
            v += __shfl_xor_sync(0xffffffffu, v, 8);
            v += __shfl_xor_sync(0xffffffffu, v, 16);
            cs[n8][j] = v;
        }

    if (g < 4) {
        float o0 = 0.f, o1 = 0.f;
        #pragma unroll
        for (int n8 = 0; n8 < 4; n8++)
            if (n8 == g) { o0 = cs[n8][0]; o1 = cs[n8][1]; }
        // NOTE: h*32 offset is load-bearing (Round-10 regression)
        *(float2*)&know[(long)b * CC + h * 32 + g * 8 + 2 * tg] = make_float2(o0, o1);
    }
}

// ---------------------------------------------------------------------------
// Fused kernel: L1a GEMM blocks (0..255, 2-stage, CVTA from raw x) +
//               knowledge blocks (256..2303).
// Union static smem: max(gemm 2*(64*36+32*72)=9216, knowledge 64*72+4*16*68
// = 8960) floats = 9216 floats = 36.9 KB.
// ---------------------------------------------------------------------------
#define L1A_BLOCKS 256
__global__ void __launch_bounds__(256) fused_l1a_know_kernel(
    const float* __restrict__ x, const float* __restrict__ w1a,
    const float* __restrict__ b1a, float* __restrict__ h1,
    const float* __restrict__ kg, const float* __restrict__ Wkg,
    const float* __restrict__ bkg, const int* __restrict__ cidx,
    const int* __restrict__ cnt, float* __restrict__ know)
{
    __shared__ __align__(16) float smem[9216];
    if (blockIdx.x < L1A_BLOCKS) {
        gemm_body<64, 32, 2, true, false, true, 1, false>(
            smem, blockIdx.x & 1, blockIdx.x >> 1,
            x, nullptr, nullptr, w1a, b1a, nullptr, h1, B_SZ, 128, IN_SZ, IN_SZ);
    } else {
        knowledge_body(smem, blockIdx.x - L1A_BLOCKS, kg, Wkg, bkg, cidx, cnt, know);
    }
}

// ---------------------------------------------------------------------------
// Standalone GEMM kernel wrappers
// ---------------------------------------------------------------------------
template <int BM_, int BK_, int STAGES, bool RELU, bool ADDK, bool ROUND>
__global__ void __launch_bounds__(256) tgemm2_kernel(
    const float* __restrict__ A, const float* __restrict__ W,
    const float* __restrict__ bias, const float* __restrict__ addk,
    float* __restrict__ C, int M, int N, int K)
{
    constexpr int SM_FLOATS = STAGES * (BM_ * (BK_ + 4) + BK_ * 72);
    __shared__ __align__(16) float smem[SM_FLOATS];
    gemm_body<BM_, BK_, STAGES, RELU, ADDK, ROUND, 0, false>(
        smem, blockIdx.x, blockIdx.y, A, nullptr, nullptr, W, bias, addk,
        C, M, N, K, K);
}

// Split-K partial GEMM: blockIdx.z selects K-half; raw fp32 partial output.
__global__ void __launch_bounds__(256) tgemm_part_kernel(
    const float* __restrict__ A, const float* __restrict__ W,
    float* __restrict__ C, int M, int N, int KH, int lda)
{
    constexpr int SM_FLOATS = 2 * (64 * 36 + 32 * 72);
    __shared__ __align__(16) float smem[SM_FLOATS];
    int z = blockIdx.z;
    gemm_body<64, 32, 2, false, false, false, 0, true>(
        smem, blockIdx.x, blockIdx.y,
        A + (long)z * KH, nullptr, nullptr,
        W + (long)z * KH * N, nullptr, nullptr,
        C + (long)z * M * N, M, N, KH, lda);
}

// Fused split-K reduce + bias + relu (previous layer) in A-staging.
__global__ void __launch_bounds__(256) tgemm_suma_kernel(
    const float* __restrict__ P0, const float* __restrict__ P1,
    const float* __restrict__ biasK, const float* __restrict__ W,
    const float* __restrict__ bias, const float* __restrict__ addk,
    float* __restrict__ C, int M, int N, int K)
{
    constexpr int SM_FLOATS = 2 * (64 * 36 + 32 * 72);
    __shared__ __align__(16) float smem[SM_FLOATS];
    gemm_body<64, 32, 2, true, true, true, 2, false>(
        smem, blockIdx.x, blockIdx.y, P0, P1, biasK, W, bias, addk,
        C, M, N, K, K);
}

// ---------------------------------------------------------------------------
// Launcher
// Input order (metadata): x, kg, idx, mask, Wkg, bkg, W1a,b1a, W1b,b1b,
//                         W1c,b1c, W1d,b1d, W2,b2.  Output: float [8192,1024].
// ---------------------------------------------------------------------------
extern "C" void kernel_launch(void* const* d_in, const int* in_sizes, int n_in,
                              void* d_out, int out_size)
{
    const float* x    = (const float*)d_in[0];
    const float* kg   = (const float*)d_in[1];
    const int*   idx  = (const int*)  d_in[2];
    const int*   mask = (const int*)  d_in[3];
    const float* Wkg  = (const float*)d_in[4];
    const float* bkg  = (const float*)d_in[5];
    const float* W1a  = (const float*)d_in[6];
    const float* b1a  = (const float*)d_in[7];
    const float* W1b  = (const float*)d_in[8];
    const float* b1b  = (const float*)d_in[9];
    const float* W1c  = (const float*)d_in[10];
    const float* b1c  = (const float*)d_in[11];
    const float* W1d  = (const float*)d_in[12];
    const float* b1d  = (const float*)d_in[13];
    const float* W2   = (const float*)d_in[14];
    const float* b2   = (const float*)d_in[15];
    float* out = (float*)d_out;

    float *h1, *h2, *h3p, *h4, *know, *wt;
    int *cnt, *cidx;
    cudaGetSymbolAddress((void**)&h1,   g_h1);
    cudaGetSymbolAddress((void**)&h2,   g_h2);
    cudaGetSymbolAddress((void**)&h3p,  g_h3p);
    cudaGetSymbolAddress((void**)&h4,   g_h4);
    cudaGetSymbolAddress((void**)&know, g_know);
    cudaGetSymbolAddress((void**)&wt,   g_wt);
    cudaGetSymbolAddress((void**)&cnt,  g_cnt);
    cudaGetSymbolAddress((void**)&cidx, g_cidx);

    // 1) setup: mask compaction (1024 blocks) + weight tf32 cvt (264 blocks)
    setup_kernel<<<1288, 256>>>(idx, mask, cidx, cnt, W1a, W1b, W1c, W1d, W2);
    // 2) fused: L1a GEMM (256 blocks, CVTA from raw x) || knowledge (2048 blocks)
    fused_l1a_know_kernel<<<L1A_BLOCKS + B_SZ / 4, 256>>>(
        x, wt + W1A_OFF, b1a, h1, kg, Wkg, bkg, cidx, cnt, know);
    // 3) L1b: [8192,128] @ [128,512]  BM=128/BK=16, 3-stage pipeline
    tgemm2_kernel<128, 16, 3, true, false, true><<<dim3(512 / 64, B_SZ / 128), 256>>>(
        h1, wt + W1B_OFF, b1b, nullptr, h2, B_SZ, 512, 128);
    // 4) L1c split-K: [8192,512] @ [512,128] -> two K=256 partials, 512 blocks
    tgemm_part_kernel<<<dim3(128 / 64, B_SZ / 64, 2), 256>>>(
        h2, wt + W1C_OFF, h3p, B_SZ, 128, 256, 512);
    // 5) L1d: A = relu(p0+p1+b1c) fused in staging; [8192,128]@[128,64] + know
    tgemm_suma_kernel<<<dim3(CC / 64, B_SZ / 64), 256>>>(
        h3p, h3p + (long)B_SZ * 128, b1c, wt + W1D_OFF, b1d, know,
        h4, B_SZ, CC, 128);
    // 6) L2: [8192,64] @ [64,1024]  BM=128/BK=16, 3-stage (fp32 out)
    tgemm2_kernel<128, 16, 3, false, false, false><<<dim3(OUT_SZ / 64, B_SZ / 128), 256>>>(
        h4, wt + W2_OFF, b2, nullptr, out, B_SZ, OUT_SZ, CC);
}